// round 3
// baseline (speedup 1.0000x reference)
#include <cuda_runtime.h>
#include <cuda_bf16.h>
#include <math.h>

#define D_    256
#define NB    64
#define SEQ   1024
#define EPSV  1e-10f
#define SWEEPS 8
#define NIT    16

// closed-form constants
#define ALPHA     0.32768f        // (1-2*ETA)^5
#define ALPHA2_64 0.0016777216f   // ALPHA^2 / 64
#define ALPHA_8   0.04096f        // ALPHA / 8
#define BETA      0.59049f        // (1-ETA)^5
#define OMBETA    0.40951f        // 1 - BETA

// ---------------- device scratch (no allocations allowed) ----------------
__device__ float g_bm[D_];              // bubble mean
__device__ float g_D0[NB * D_];         // deviations
__device__ float g_Gg[NB * NB];         // Gram matrix
__device__ float g_Wg[NB * NB];         // Jacobi eigenvectors (columns)
__device__ float g_UT[NB * D_];         // UT[k][d]: eigvec k of A (63 used)
__device__ float g_poles[NB];           // poles[0]=0, poles[1..63] ascending
__device__ int   g_colperm[NB];         // kept-eig slot -> Jacobi column
__device__ float g_trA;                 // sum of kept poles
__device__ float g_decay;
__device__ float g_X[SEQ * D_];         // gathered embeddings
__device__ float g_M[SEQ * D_];         // m_t per step
__device__ float g_W2[SEQ * NB];        // secular weights^2 per step
__device__ float g_trace[SEQ];          // trace of unnormalized rho

// ---------------- 1) bubble mean, deviations, decay ----------------
__global__ void k_setup(const float* __restrict__ bubbles,
                        const float* __restrict__ mdecay) {
    int d = threadIdx.x;   // 256 threads
    if (d == 0) g_decay = 1.f / (1.f + expf(-mdecay[0]));
    float s = 0.f;
#pragma unroll
    for (int i = 0; i < NB; i++) s += bubbles[i * D_ + d];
    float bm = s * (1.f / NB);
    g_bm[d] = bm;
#pragma unroll
    for (int i = 0; i < NB; i++) g_D0[i * D_ + d] = bubbles[i * D_ + d] - bm;
}

// ---------------- 2) G = (alpha^2/64) * D0 D0^T  (64x64) ----------------
__global__ void k_gram() {            // <<<64, 64>>>
    __shared__ float rowi[D_];
    int i = blockIdx.x, j = threadIdx.x;
    for (int dd = j; dd < D_; dd += 64) rowi[dd] = g_D0[i * D_ + dd];
    __syncthreads();
    float acc = 0.f;
#pragma unroll 4
    for (int dd = 0; dd < D_; dd++) acc += rowi[dd] * g_D0[j * D_ + dd];
    g_Gg[i * NB + j] = acc * ALPHA2_64;
}

// ---------------- 3) parallel (tournament) Jacobi on 64x64 ----------------
__global__ void k_jacobi() {          // <<<1, 1024>>>
    __shared__ float G[NB * 65];      // pitch 65 avoids bank conflicts
    __shared__ float W[NB * 65];
    __shared__ float cs[32], sn[32];
    __shared__ int   pp[32], qq[32];
    __shared__ float dval[NB];
    int tid = threadIdx.x;

    for (int e = tid; e < NB * NB; e += 1024) {
        int i = e >> 6, j = e & 63;
        G[i * 65 + j] = g_Gg[e];
        W[i * 65 + j] = (i == j) ? 1.f : 0.f;
    }
    __syncthreads();

    for (int sweep = 0; sweep < SWEEPS; sweep++) {
        for (int r = 0; r < 63; r++) {
            if (tid < 32) {
                int p, q;
                if (tid == 0) { p = 63; q = r; }
                else { p = (r + tid) % 63; q = (r - tid + 63) % 63; }
                if (p > q) { int tmp = p; p = q; q = tmp; }
                float app = G[p * 65 + p], aqq = G[q * 65 + q], apq = G[p * 65 + q];
                float c = 1.f, s = 0.f;
                if (fabsf(apq) > 1e-12f) {
                    float tau = (aqq - app) / (2.f * apq);
                    float tt = (tau >= 0.f ? 1.f : -1.f) /
                               (fabsf(tau) + sqrtf(1.f + tau * tau));
                    c = rsqrtf(1.f + tt * tt);
                    s = tt * c;
                }
                cs[tid] = c; sn[tid] = s; pp[tid] = p; qq[tid] = q;
            }
            __syncthreads();
            // phase A: column rotations on G and W  (G <- G*J, W <- W*J)
            for (int e = tid; e < 2048; e += 1024) {
                int i = e & 63, pr = e >> 6;
                int p = pp[pr], q = qq[pr];
                float c = cs[pr], s = sn[pr];
                float gp = G[i * 65 + p], gq = G[i * 65 + q];
                G[i * 65 + p] = c * gp - s * gq;
                G[i * 65 + q] = s * gp + c * gq;
                float wp = W[i * 65 + p], wq = W[i * 65 + q];
                W[i * 65 + p] = c * wp - s * wq;
                W[i * 65 + q] = s * wp + c * wq;
            }
            __syncthreads();
            // phase B: row rotations on G  (G <- J^T * G)
            for (int e = tid; e < 2048; e += 1024) {
                int j = e & 63, pr = e >> 6;
                int p = pp[pr], q = qq[pr];
                float c = cs[pr], s = sn[pr];
                float gp = G[p * 65 + j], gq = G[q * 65 + j];
                G[p * 65 + j] = c * gp - s * gq;
                G[q * 65 + j] = s * gp + c * gq;
            }
            __syncthreads();
        }
    }

    if (tid < NB) dval[tid] = G[tid * 65 + tid];
    __syncthreads();
    // sort by rank; drop the single minimum (the exact-zero 1-vector mode)
    if (tid < NB) {
        float v = dval[tid];
        int rk = 0;
        for (int j = 0; j < NB; j++) {
            float u = dval[j];
            if (u < v || (u == v && j < tid)) rk++;
        }
        if (rk > 0) {                      // keep ranks 1..63
            g_poles[rk] = fmaxf(v, 1e-12f);
            g_colperm[rk - 1] = tid;
        }
    }
    if (tid == 0) g_poles[0] = 0.f;
    __syncthreads();
    if (tid == 0) {
        float s = 0.f;
        for (int k = 1; k < NB; k++) s += g_poles[k];
        g_trA = s;
    }
    for (int e = tid; e < NB * NB; e += 1024)
        g_Wg[e] = W[(e >> 6) * 65 + (e & 63)];
}

// ---------------- 4) build U^T (eigvecs of A = normalized D0^T w) --------
__global__ void k_buildU() {          // <<<63, 256>>>
    __shared__ float wcol[NB];
    int k = blockIdx.x, d = threadIdx.x;
    if (d < NB) wcol[d] = g_Wg[d * NB + g_colperm[k]];
    __syncthreads();
    float acc = 0.f;
#pragma unroll 8
    for (int i = 0; i < NB; i++) acc += g_D0[i * D_ + d] * wcol[i];
    float lam = g_poles[k + 1];
    g_UT[k * D_ + d] = acc * ALPHA_8 * rsqrtf(fmaxf(lam, 1e-20f));
}

// ---------------- 5) gather token embeddings ----------------
__global__ void k_gather(const int* __restrict__ tokens,
                         const float* __restrict__ embed) {  // <<<1024, 256>>>
    int t = blockIdx.x, d = threadIdx.x;
    g_X[t * D_ + d] = embed[(long)tokens[t] * D_ + d];
}

// ---------------- 6) sequential memory scan (per-component) ----------------
__global__ void k_scan() {            // <<<1, 256>>>
    int d = threadIdx.x;
    float decay = g_decay;
    float omdecay = 1.f - decay;
    float cb = BETA * g_bm[d];
    float mm = 0.f;
    float xs[8];
#pragma unroll
    for (int j = 0; j < 8; j++) xs[j] = g_X[j * D_ + d];
    for (int t0 = 0; t0 < SEQ; t0 += 8) {
#pragma unroll
        for (int j = 0; j < 8; j++) {
            float x = xs[j];
            int tn = t0 + 8 + j;
            if (tn < SEQ) xs[j] = g_X[tn * D_ + d];
            float m = cb + OMBETA * (x + decay * mm);
            g_M[(t0 + j) * D_ + d] = m;
            mm = decay * mm + omdecay * m;
        }
    }
}

// ---------------- 7) per-step secular weights ----------------
__global__ void k_weights() {         // <<<1024, 256>>>
    __shared__ float sm[D_];
    __shared__ float zsh[64];
    __shared__ float red[8];
    int t = blockIdx.x, tid = threadIdx.x;
    int warp = tid >> 5, lane = tid & 31;

    float mv = g_M[t * D_ + tid];
    sm[tid] = mv;
    float p = mv * mv;
#pragma unroll
    for (int off = 16; off > 0; off >>= 1)
        p += __shfl_down_sync(0xFFFFFFFFu, p, off);
    if (lane == 0) red[warp] = p;
    __syncthreads();

    // z_k = U_k . m  for k = 0..62 (warp-per-k, 8 per warp)
#pragma unroll
    for (int it = 0; it < 8; it++) {
        int k = warp * 8 + it;
        if (k < 63) {
            float acc = 0.f;
#pragma unroll
            for (int j = 0; j < 8; j++)
                acc += g_UT[k * D_ + lane + 32 * j] * sm[lane + 32 * j];
#pragma unroll
            for (int off = 16; off > 0; off >>= 1)
                acc += __shfl_down_sync(0xFFFFFFFFu, acc, off);
            if (lane == 0) zsh[k] = acc;
        }
    }
    __syncthreads();

    if (tid == 0) {
        float msq = 0.f;
#pragma unroll
        for (int w = 0; w < 8; w++) msq += red[w];
        float sz = 0.f;
        for (int k = 0; k < 63; k++) sz += zsh[k] * zsh[k];
        g_W2[t * NB] = fmaxf(msq - sz, 0.f);      // r^2, pole 0
        g_trace[t] = msq + g_trA;
    } else if (tid < 64) {
        float z = zsh[tid - 1];
        g_W2[t * NB + tid] = z * z;
    }
}

// ---------------- 8) secular equation roots + output ----------------
__global__ void k_secular(float* __restrict__ out) {  // <<<1024, 64>>>
    __shared__ float w2s[NB], ds[NB], vals[NB];
    int t = blockIdx.x, i = threadIdx.x;   // 64 threads
    w2s[i] = g_W2[t * NB + i];
    ds[i]  = g_poles[i];
    __syncthreads();

    float S = 0.f;
#pragma unroll 8
    for (int k = 0; k < NB; k++) S += w2s[k];

    float lo = ds[i];
    float hi = (i < 63) ? ds[i + 1] : ds[63] + S;
    float lam = 0.5f * (lo + hi);

    for (int it = 0; it < NIT; it++) {
        float f = 1.f, fp = 0.f;
#pragma unroll 8
        for (int k = 0; k < NB; k++) {
            float diff = ds[k] - lam;
            float rc;
            asm("rcp.approx.f32 %0, %1;" : "=f"(rc) : "f"(diff));
            float term = w2s[k] * rc;
            f  += term;
            fp += term * rc;
        }
        if (f > 0.f) hi = lam; else lo = lam;
        float ln = lam - __fdividef(f, fp);
        lam = (ln > lo && ln < hi) ? ln : 0.5f * (lo + hi);
    }

    float tr = g_trace[t];
    float v = fmaxf(__fdividef(lam, tr), EPSV);
    vals[i] = v;
    __syncthreads();

    float ssum = 192.f * EPSV;
#pragma unroll 8
    for (int k = 0; k < NB; k++) ssum += vals[k];
    float inv = __frcp_rn(ssum);

    float* o = out + (long)t * D_;
    float ev = EPSV * inv;
    o[i]        = ev;               // positions   0..63  (zero eigs)
    o[i + 64]   = ev;               // positions  64..127
    o[i + 128]  = ev;               // positions 128..191
    o[i + 192]  = vals[i] * inv;    // positions 192..255 (roots, ascending)
}

// ---------------- launcher ----------------
extern "C" void kernel_launch(void* const* d_in, const int* in_sizes, int n_in,
                              void* d_out, int out_size) {
    const int*   tokens = (const int*)d_in[0];
    const float* embed  = (const float*)d_in[1];
    const float* bubbles= (const float*)d_in[2];
    const float* mdecay = (const float*)d_in[3];
    float* out = (float*)d_out;

    k_setup  <<<1,    256>>>(bubbles, mdecay);
    k_gram   <<<64,   64>>>();
    k_jacobi <<<1,    1024>>>();
    k_buildU <<<63,   256>>>();
    k_gather <<<SEQ,  256>>>(tokens, embed);
    k_scan   <<<1,    256>>>();
    k_weights<<<SEQ,  256>>>();
    k_secular<<<SEQ,  64>>>(out);
    (void)in_sizes; (void)n_in; (void)out_size;
}

// round 4
// speedup vs baseline: 1.3922x; 1.3922x over previous
#include <cuda_runtime.h>
#include <cuda_bf16.h>
#include <math.h>

#define D_    256
#define NB    64
#define SEQ   1024
#define EPSV  1e-10f
#define SWEEPS 7
#define NIT    16

// closed-form constants
#define ALPHA     0.32768f        // (1-2*ETA)^5
#define ALPHA2_64 0.0016777216f   // ALPHA^2 / 64
#define ALPHA_8   0.04096f        // ALPHA / 8
#define BETA      0.59049f        // (1-ETA)^5
#define OMBETA    0.40951f        // 1 - BETA

// ---------------- device scratch (no allocations allowed) ----------------
__device__ float g_bm[D_];              // bubble mean
__device__ float g_D0[NB * D_];         // deviations
__device__ float g_Gg[NB * NB];         // Gram matrix
__device__ float g_Wg[NB * NB];         // Jacobi eigenvectors (columns)
__device__ float g_UT[NB * D_];         // UT[k][d]: eigvec k of A (63 used)
__device__ float g_poles[NB];           // poles[0]=0, poles[1..63] ascending
__device__ int   g_colperm[NB];         // kept-eig slot -> Jacobi column
__device__ float g_trA;                 // sum of kept poles
__device__ float g_decay;
__device__ float g_X[SEQ * D_];         // gathered embeddings
__device__ float g_M[SEQ * D_];         // m_t per step

// ---------------- 1) bubble mean, deviations, decay ----------------
__global__ void k_setup(const float* __restrict__ bubbles,
                        const float* __restrict__ mdecay) {
    int d = threadIdx.x;   // 256 threads
    if (d == 0) g_decay = 1.f / (1.f + expf(-mdecay[0]));
    float s = 0.f;
#pragma unroll
    for (int i = 0; i < NB; i++) s += bubbles[i * D_ + d];
    float bm = s * (1.f / NB);
    g_bm[d] = bm;
#pragma unroll
    for (int i = 0; i < NB; i++) g_D0[i * D_ + d] = bubbles[i * D_ + d] - bm;
}

// ---------------- 2) G = (alpha^2/64) * D0 D0^T  (64x64) ----------------
__global__ void k_gram() {            // <<<64, 64>>>
    __shared__ float rowi[D_];
    int i = blockIdx.x, j = threadIdx.x;
    for (int dd = j; dd < D_; dd += 64) rowi[dd] = g_D0[i * D_ + dd];
    __syncthreads();
    float acc = 0.f;
#pragma unroll 4
    for (int dd = 0; dd < D_; dd++) acc += rowi[dd] * g_D0[j * D_ + dd];
    g_Gg[i * NB + j] = acc * ALPHA2_64;
}

// ---------------- 3) warp-per-pair tournament Jacobi on 64x64 ----------------
__global__ void k_jacobi() {          // <<<1, 1024>>>
    __shared__ float G[NB * 65];      // pitch 65: stride-65 column access is conflict-free
    __shared__ float W[NB * 65];
    __shared__ float dval[NB];
    int tid  = threadIdx.x;
    int warp = tid >> 5, lane = tid & 31;

    for (int e = tid; e < NB * NB; e += 1024) {
        int i = e >> 6, j = e & 63;
        G[i * 65 + j] = g_Gg[e];
        W[i * 65 + j] = (i == j) ? 1.f : 0.f;
    }
    __syncthreads();

    for (int sweep = 0; sweep < SWEEPS; sweep++) {
        for (int r = 0; r < 63; r++) {
            // this warp's tournament pair (compile-time schedule, circle method)
            int p, q;
            if (warp == 0) { p = 63; q = r; }
            else { p = (r + warp) % 63; q = (r - warp + 63) % 63; }
            if (p > q) { int tmp = p; p = q; q = tmp; }

            // rotation params, computed redundantly in all lanes (smem broadcast)
            float app = G[p * 65 + p], aqq = G[q * 65 + q], apq = G[p * 65 + q];
            float c = 1.f, s = 0.f;
            if (fabsf(apq) > 1e-12f) {
                float tau = __fdividef(aqq - app, 2.f * apq);
                float t2  = 1.f + tau * tau;
                float sq  = t2 * rsqrtf(t2);          // ~sqrt(1+tau^2)
                float tt  = __fdividef(tau >= 0.f ? 1.f : -1.f,
                                       fabsf(tau) + sq);
                c = rsqrtf(1.f + tt * tt);
                s = tt * c;
            }

            // phase A: rotate columns p,q of G and W (rows split across lanes)
#pragma unroll
            for (int h = 0; h < 2; h++) {
                int i = lane + 32 * h;
                float gp = G[i * 65 + p], gq = G[i * 65 + q];
                G[i * 65 + p] = c * gp - s * gq;
                G[i * 65 + q] = s * gp + c * gq;
                float wp = W[i * 65 + p], wq = W[i * 65 + q];
                W[i * 65 + p] = c * wp - s * wq;
                W[i * 65 + q] = s * wp + c * wq;
            }
            __syncthreads();
            // phase B: rotate rows p,q of G
#pragma unroll
            for (int h = 0; h < 2; h++) {
                int j = lane + 32 * h;
                float gp = G[p * 65 + j], gq = G[q * 65 + j];
                G[p * 65 + j] = c * gp - s * gq;
                G[q * 65 + j] = s * gp + c * gq;
            }
            __syncthreads();
        }
    }

    if (tid < NB) dval[tid] = G[tid * 65 + tid];
    __syncthreads();
    // rank-sort; drop the single minimum (the exact-zero 1-vector mode)
    if (tid < NB) {
        float v = dval[tid];
        int rk = 0;
        for (int j = 0; j < NB; j++) {
            float u = dval[j];
            if (u < v || (u == v && j < tid)) rk++;
        }
        if (rk > 0) {                      // keep ranks 1..63
            g_poles[rk] = fmaxf(v, 1e-12f);
            g_colperm[rk - 1] = tid;
        }
    }
    if (tid == 0) g_poles[0] = 0.f;
    __syncthreads();
    if (tid == 0) {
        float s = 0.f;
        for (int k = 1; k < NB; k++) s += g_poles[k];
        g_trA = s;
    }
    for (int e = tid; e < NB * NB; e += 1024)
        g_Wg[e] = W[(e >> 6) * 65 + (e & 63)];
}

// ---------------- 4) build U^T (eigvecs of A = normalized D0^T w) --------
__global__ void k_buildU() {          // <<<63, 256>>>
    __shared__ float wcol[NB];
    int k = blockIdx.x, d = threadIdx.x;
    if (d < NB) wcol[d] = g_Wg[d * NB + g_colperm[k]];
    __syncthreads();
    float acc = 0.f;
#pragma unroll 8
    for (int i = 0; i < NB; i++) acc += g_D0[i * D_ + d] * wcol[i];
    float lam = g_poles[k + 1];
    g_UT[k * D_ + d] = acc * ALPHA_8 * rsqrtf(fmaxf(lam, 1e-20f));
}

// ---------------- 5) gather token embeddings ----------------
__global__ void k_gather(const int* __restrict__ tokens,
                         const float* __restrict__ embed) {  // <<<1024, 256>>>
    int t = blockIdx.x, d = threadIdx.x;
    g_X[t * D_ + d] = embed[(long)tokens[t] * D_ + d];
}

// ---------------- 6) sequential memory scan (per-component) ----------------
__global__ void k_scan() {            // <<<1, 256>>>
    int d = threadIdx.x;
    float decay = g_decay;
    float omdecay = 1.f - decay;
    float cb = BETA * g_bm[d];
    float mm = 0.f;
    float xs[8];
#pragma unroll
    for (int j = 0; j < 8; j++) xs[j] = g_X[j * D_ + d];
    for (int t0 = 0; t0 < SEQ; t0 += 8) {
#pragma unroll
        for (int j = 0; j < 8; j++) {
            float x = xs[j];
            int tn = t0 + 8 + j;
            if (tn < SEQ) xs[j] = g_X[tn * D_ + d];
            float m = cb + OMBETA * (x + decay * mm);
            g_M[(t0 + j) * D_ + d] = m;
            mm = decay * mm + omdecay * m;
        }
    }
}

// ---------------- 7) fused weights + secular roots + output ----------------
__global__ void k_wsec(float* __restrict__ out) {  // <<<1024, 256>>>
    __shared__ float sm[D_];
    __shared__ float zsh[64];
    __shared__ float red[8];
    __shared__ float w2s[NB], ds[NB], vals[NB];
    int t = blockIdx.x, tid = threadIdx.x;
    int warp = tid >> 5, lane = tid & 31;

    float mv = g_M[t * D_ + tid];
    sm[tid] = mv;
    float p = mv * mv;
#pragma unroll
    for (int off = 16; off > 0; off >>= 1)
        p += __shfl_down_sync(0xFFFFFFFFu, p, off);
    if (lane == 0) red[warp] = p;
    if (tid < NB) ds[tid] = g_poles[tid];
    __syncthreads();

    // z_k = U_k . m  for k = 0..62 (warp-per-k, 8 per warp)
#pragma unroll
    for (int it = 0; it < 8; it++) {
        int k = warp * 8 + it;
        if (k < 63) {
            float acc = 0.f;
#pragma unroll
            for (int j = 0; j < 8; j++)
                acc += g_UT[k * D_ + lane + 32 * j] * sm[lane + 32 * j];
#pragma unroll
            for (int off = 16; off > 0; off >>= 1)
                acc += __shfl_down_sync(0xFFFFFFFFu, acc, off);
            if (lane == 0) zsh[k] = acc;
        }
    }
    __syncthreads();

    // weights (threads 0..63)
    float msq = 0.f;
#pragma unroll
    for (int w = 0; w < 8; w++) msq += red[w];
    if (tid == 0) {
        float sz = 0.f;
        for (int k = 0; k < 63; k++) sz += zsh[k] * zsh[k];
        w2s[0] = fmaxf(msq - sz, 0.f);           // r^2, pole 0
    } else if (tid < 64) {
        float z = zsh[tid - 1];
        w2s[tid] = z * z;
    }
    __syncthreads();

    if (tid >= 64) return;   // past the last barrier, safe to retire

    int i = tid;
    float S = 0.f;
#pragma unroll 8
    for (int k = 0; k < NB; k++) S += w2s[k];

    float lo = ds[i];
    float hi = (i < 63) ? ds[i + 1] : ds[63] + S;
    float lam = 0.5f * (lo + hi);

    for (int it = 0; it < NIT; it++) {
        float f = 1.f, fp = 0.f;
#pragma unroll 8
        for (int k = 0; k < NB; k++) {
            float diff = ds[k] - lam;
            float rc;
            asm("rcp.approx.f32 %0, %1;" : "=f"(rc) : "f"(diff));
            float term = w2s[k] * rc;
            f  += term;
            fp += term * rc;
        }
        if (f > 0.f) hi = lam; else lo = lam;
        float ln = lam - __fdividef(f, fp);
        lam = (ln > lo && ln < hi) ? ln : 0.5f * (lo + hi);
    }

    float tr = msq + g_trA;
    float v = fmaxf(__fdividef(lam, tr), EPSV);
    vals[i] = v;
    __syncwarp();
    // sum across the 64 roots: vals written by 2 warps; need both visible
    __threadfence_block();
    // cheap 2-warp sync via shfl-free smem read after volatile pattern:
    // use a named barrier over the first 64 threads
    asm volatile("bar.sync 1, 64;" ::: "memory");

    float ssum = 192.f * EPSV;
#pragma unroll 8
    for (int k = 0; k < NB; k++) ssum += vals[k];
    float inv = __frcp_rn(ssum);

    float* o = out + (long)t * D_;
    float ev = EPSV * inv;
    o[i]        = ev;               // positions   0..63  (zero eigs)
    o[i + 64]   = ev;               // positions  64..127
    o[i + 128]  = ev;               // positions 128..191
    o[i + 192]  = vals[i] * inv;    // positions 192..255 (roots, ascending)
}

// ---------------- launcher ----------------
extern "C" void kernel_launch(void* const* d_in, const int* in_sizes, int n_in,
                              void* d_out, int out_size) {
    const int*   tokens = (const int*)d_in[0];
    const float* embed  = (const float*)d_in[1];
    const float* bubbles= (const float*)d_in[2];
    const float* mdecay = (const float*)d_in[3];
    float* out = (float*)d_out;

    k_setup  <<<1,    256>>>(bubbles, mdecay);
    k_gram   <<<64,   64>>>();
    k_jacobi <<<1,    1024>>>();
    k_buildU <<<63,   256>>>();
    k_gather <<<SEQ,  256>>>(tokens, embed);
    k_scan   <<<1,    256>>>();
    k_wsec   <<<SEQ,  256>>>(out);
    (void)in_sizes; (void)n_in; (void)out_size;
}

// round 6
// speedup vs baseline: 2.0433x; 1.4676x over previous
#include <cuda_runtime.h>
#include <cuda_bf16.h>
#include <math.h>

#define D_    256
#define NB    64
#define SEQ   1024
#define EPSV  1e-10f
#define NIT   12
#define NITB  26

// closed-form constants
#define ALPHA     0.32768f        // (1-2*ETA)^5
#define ALPHA2_64 0.0016777216f   // ALPHA^2 / 64
#define ALPHA_8   0.04096f        // ALPHA / 8
#define BETA      0.59049f        // (1-ETA)^5
#define OMBETA    0.40951f        // 1 - BETA

// ---------------- device scratch (no allocations allowed) ----------------
__device__ float g_bm[D_];              // bubble mean
__device__ float g_D0[NB * D_];         // deviations
__device__ float g_Gg[NB * NB];         // Gram matrix
__device__ float g_Wg[NB * NB];         // eigenvectors of G (columns, ascending)
__device__ float g_UT[NB * D_];         // UT[k][d]: eigvec k of A (63 used)
__device__ float g_poles[NB];           // poles[0]=0, poles[1..63] ascending
__device__ float g_trA;                 // sum of kept poles
__device__ float g_decay;
__device__ float g_X[SEQ * D_];         // gathered embeddings
__device__ float g_M[SEQ * D_];         // m_t per step

// ---------------- 1) bubble mean, deviations, decay ----------------
__global__ void k_setup(const float* __restrict__ bubbles,
                        const float* __restrict__ mdecay) {
    int d = threadIdx.x;   // 256 threads
    if (d == 0) g_decay = 1.f / (1.f + expf(-mdecay[0]));
    float s = 0.f;
#pragma unroll
    for (int i = 0; i < NB; i++) s += bubbles[i * D_ + d];
    float bm = s * (1.f / NB);
    g_bm[d] = bm;
#pragma unroll
    for (int i = 0; i < NB; i++) g_D0[i * D_ + d] = bubbles[i * D_ + d] - bm;
}

// ---------------- 2) G = (alpha^2/64) * D0 D0^T  (64x64) ----------------
__global__ void k_gram() {            // <<<64, 64>>>
    __shared__ float rowi[D_];
    int i = blockIdx.x, j = threadIdx.x;
    for (int dd = j; dd < D_; dd += 64) rowi[dd] = g_D0[i * D_ + dd];
    __syncthreads();
    float acc = 0.f;
#pragma unroll 4
    for (int dd = 0; dd < D_; dd++) acc += rowi[dd] * g_D0[j * D_ + dd];
    g_Gg[i * NB + j] = acc * ALPHA2_64;
}

// ------- 3) eigensolver: Householder tridiag + bisection + invit --------
__global__ void k_eigen() {           // <<<1, 1024, 66560>>>
    extern __shared__ float sm[];
    float* A  = sm;                   // 64x65  (G; lower cols become v's)
    float* E  = sm + 4160;            // 64x65  (eigvec columns)
    float* DD = sm + 8320;            // 64x65  invit scratch (per-thread rows)
    float* YY = sm + 12480;           // 64x65  invit scratch

    __shared__ float diag[64], off[64], b2[64], eig[64], tauv[64];
    __shared__ float parr[64], warr[64], red[32];
    __shared__ float gl[64], gh[64];
    __shared__ float sc_tau, sc_K, sc_lo, sc_hi;

    int tid = threadIdx.x, lane = tid & 31, warp = tid >> 5;

    for (int e = tid; e < NB * NB; e += 1024)
        A[(e >> 6) * 65 + (e & 63)] = g_Gg[e];
    __syncthreads();

    // ---- Householder tridiagonalization ----
    for (int k = 0; k < 62; k++) {
        int n0 = k + 1, n2 = 63 - k;
        // |x|^2 where x = A[n0..63, k]
        float xv = (tid < n2) ? A[(n0 + tid) * 65 + k] : 0.f;
        float s = xv * xv;
#pragma unroll
        for (int o = 16; o > 0; o >>= 1) s += __shfl_down_sync(0xFFFFFFFFu, s, o);
        if (lane == 0) red[warp] = s;
        __syncthreads();
        if (tid == 0) {
            float sum = red[0] + red[1];
            float x0 = A[n0 * 65 + k];
            float sigma = sqrtf(sum);
            float sgn = (x0 >= 0.f) ? 1.f : -1.f;
            float v0 = x0 + sgn * sigma;
            float tau = (sigma > 1e-30f)
                      ? 1.f / (sigma * (sigma + fabsf(x0))) : 0.f;
            sc_tau = tau;
            tauv[k] = tau;
            off[k] = -sgn * sigma;
            A[n0 * 65 + k] = v0;       // column k now holds v
        }
        __syncthreads();
        // p = tau * Asub * v
        if (tid < n2) {
            float acc = 0.f;
            const float* arow = &A[(n0 + tid) * 65 + n0];
            for (int c = 0; c < n2; c++)
                acc += arow[c] * A[(n0 + c) * 65 + k];
            parr[tid] = acc * sc_tau;
        }
        __syncthreads();
        // K = tau * (v . p) / 2      <-- the R5 bug: tau was missing
        float pv = (tid < n2) ? parr[tid] * A[(n0 + tid) * 65 + k] : 0.f;
#pragma unroll
        for (int o = 16; o > 0; o >>= 1) pv += __shfl_down_sync(0xFFFFFFFFu, pv, o);
        if (lane == 0) red[warp] = pv;
        __syncthreads();
        if (tid == 0) sc_K = 0.5f * sc_tau * (red[0] + red[1]);
        __syncthreads();
        if (tid < n2) warr[tid] = parr[tid] - sc_K * A[(n0 + tid) * 65 + k];
        __syncthreads();
        // A_sub -= v w^T + w v^T
        for (int e = tid; e < n2 * n2; e += 1024) {
            int i = e / n2, j = e - i * n2;
            float vi = A[(n0 + i) * 65 + k];
            float vj = A[(n0 + j) * 65 + k];
            A[(n0 + i) * 65 + (n0 + j)] -= vi * warr[j] + warr[i] * vj;
        }
        __syncthreads();
    }

    if (tid < 64) diag[tid] = A[tid * 65 + tid];
    if (tid == 0) off[62] = A[63 * 65 + 62];
    if (tid == 0) off[63] = 0.f;
    __syncthreads();
    if (tid < 63) b2[tid] = off[tid] * off[tid];
    // Gershgorin bounds
    if (tid < 64) {
        float om = (tid > 0) ? fabsf(off[tid - 1]) : 0.f;
        float op = (tid < 63) ? fabsf(off[tid]) : 0.f;
        gl[tid] = diag[tid] - om - op;
        gh[tid] = diag[tid] + om + op;
    }
    __syncthreads();
    if (tid == 0) {
        float lo = gl[0], hi = gh[0];
        for (int i = 1; i < 64; i++) {
            lo = fminf(lo, gl[i]); hi = fmaxf(hi, gh[i]);
        }
        float mg = 1e-6f * fmaxf(fabsf(lo), fabsf(hi)) + 1e-30f;
        sc_lo = lo - mg; sc_hi = hi + mg;
    }
    __syncthreads();

    // ---- bisection (thread i -> i-th smallest eigenvalue) ----
    if (tid < 64) {
        int i = tid;
        float lo = sc_lo, hi = sc_hi;
        for (int it = 0; it < NITB; it++) {
            float mid = 0.5f * (lo + hi);
            float d = diag[0] - mid;
            int cnt = (d < 0.f);
            for (int j = 1; j < 64; j++) {
                float dg = (fabsf(d) < 1e-25f) ? -1e-25f : d;
                d = (diag[j] - mid) - __fdividef(b2[j - 1], dg);
                cnt += (d < 0.f);
            }
            if (cnt <= i) lo = mid; else hi = mid;
        }
        eig[i] = 0.5f * (lo + hi);
    }
    __syncthreads();

    // ---- inverse iteration (thread i solves (T - lam I) v = b) ----
    if (tid < 64) {
        int i = tid;
        float scale = fmaxf(fabsf(sc_hi), fabsf(sc_lo));
        float lam = eig[i] + scale * 2e-6f;
        // pseudo-random start
        unsigned h = (unsigned)(i * 2654435761u) ^ 0x9E3779B9u;
        for (int j = 0; j < 64; j++) {
            h = h * 1664525u + 1013904223u;
            E[j * 65 + i] = 1.f + (float)(h >> 16) * 1.52587890625e-05f;
        }
        for (int iter = 0; iter < 3; iter++) {
            // forward elimination (no pivoting; invit self-corrects)
            float dprev = diag[0] - lam;
            dprev = (fabsf(dprev) < 1e-20f) ? copysignf(1e-20f, dprev) : dprev;
            DD[i * 65 + 0] = dprev;
            float yprev = E[0 * 65 + i];
            YY[i * 65 + 0] = yprev;
            for (int j = 1; j < 64; j++) {
                float m = __fdividef(off[j - 1], dprev);
                float dcur = (diag[j] - lam) - m * off[j - 1];
                dcur = (fabsf(dcur) < 1e-20f) ? copysignf(1e-20f, dcur) : dcur;
                float ycur = E[j * 65 + i] - m * yprev;
                DD[i * 65 + j] = dcur;
                YY[i * 65 + j] = ycur;
                dprev = dcur; yprev = ycur;
            }
            // back substitution + norm
            float vj = __fdividef(YY[i * 65 + 63], DD[i * 65 + 63]);
            E[63 * 65 + i] = vj;
            float nrm = vj * vj;
            for (int j = 62; j >= 0; j--) {
                vj = __fdividef(YY[i * 65 + j] - off[j] * vj, DD[i * 65 + j]);
                E[j * 65 + i] = vj;
                nrm += vj * vj;
            }
            float inv = rsqrtf(nrm);
            for (int j = 0; j < 64; j++) E[j * 65 + i] *= inv;
        }
    }
    __syncthreads();

    // ---- back-transform: W = H1 ... H62 * E (apply k = 61 .. 0) ----
    {
        int col = tid >> 4, sub = tid & 15;
        for (int k = 61; k >= 0; k--) {
            int n0 = k + 1, n2 = 63 - k;
            float tau = tauv[k];
            float acc = 0.f;
            for (int r = sub; r < n2; r += 16)
                acc += A[(n0 + r) * 65 + k] * E[(n0 + r) * 65 + col];
#pragma unroll
            for (int o = 8; o > 0; o >>= 1)
                acc += __shfl_xor_sync(0xFFFFFFFFu, acc, o, 16);
            float w = tau * acc;
            for (int r = sub; r < n2; r += 16)
                E[(n0 + r) * 65 + col] -= w * A[(n0 + r) * 65 + k];
            __syncthreads();
        }
    }

    // ---- publish: poles ascending (drop index 0 = null mode) ----
    if (tid == 0) {
        g_poles[0] = 0.f;
        float s = 0.f;
        for (int k = 1; k < 64; k++) {
            float p = fmaxf(eig[k], 1e-12f);
            g_poles[k] = p;
            s += p;
        }
        g_trA = s;
    }
    for (int e = tid; e < NB * NB; e += 1024)
        g_Wg[e] = E[(e >> 6) * 65 + (e & 63)];
}

// ---------------- 4) build U^T (eigvecs of A = normalized D0^T w) --------
__global__ void k_buildU() {          // <<<63, 256>>>
    __shared__ float wcol[NB];
    int k = blockIdx.x, d = threadIdx.x;
    if (d < NB) wcol[d] = g_Wg[d * NB + (k + 1)];   // ascending columns
    __syncthreads();
    float acc = 0.f;
#pragma unroll 8
    for (int i = 0; i < NB; i++) acc += g_D0[i * D_ + d] * wcol[i];
    float lam = g_poles[k + 1];
    g_UT[k * D_ + d] = acc * ALPHA_8 * rsqrtf(fmaxf(lam, 1e-20f));
}

// ---------------- 5) gather token embeddings ----------------
__global__ void k_gather(const int* __restrict__ tokens,
                         const float* __restrict__ embed) {  // <<<1024, 256>>>
    int t = blockIdx.x, d = threadIdx.x;
    g_X[t * D_ + d] = embed[(long)tokens[t] * D_ + d];
}

// ---------------- 6) sequential memory scan (per-component) ----------------
__global__ void k_scan() {            // <<<1, 256>>>
    int d = threadIdx.x;
    float decay = g_decay;
    float omdecay = 1.f - decay;
    float cb = BETA * g_bm[d];
    float mm = 0.f;
    float xs[8];
#pragma unroll
    for (int j = 0; j < 8; j++) xs[j] = g_X[j * D_ + d];
    for (int t0 = 0; t0 < SEQ; t0 += 8) {
#pragma unroll
        for (int j = 0; j < 8; j++) {
            float x = xs[j];
            int tn = t0 + 8 + j;
            if (tn < SEQ) xs[j] = g_X[tn * D_ + d];
            float m = cb + OMBETA * (x + decay * mm);
            g_M[(t0 + j) * D_ + d] = m;
            mm = decay * mm + omdecay * m;
        }
    }
}

// ---------------- 7) fused weights + secular roots + output ----------------
__global__ void k_wsec(float* __restrict__ out) {  // <<<1024, 256>>>
    __shared__ float smv[D_];
    __shared__ float zsh[64];
    __shared__ float red[8];
    __shared__ float w2s[NB], ds[NB], vals[NB];
    int t = blockIdx.x, tid = threadIdx.x;
    int warp = tid >> 5, lane = tid & 31;

    float mv = g_M[t * D_ + tid];
    smv[tid] = mv;
    float p = mv * mv;
#pragma unroll
    for (int off = 16; off > 0; off >>= 1)
        p += __shfl_down_sync(0xFFFFFFFFu, p, off);
    if (lane == 0) red[warp] = p;
    if (tid < NB) ds[tid] = g_poles[tid];
    __syncthreads();

    // z_k = U_k . m  for k = 0..62 (warp-per-k, 8 per warp)
#pragma unroll
    for (int it = 0; it < 8; it++) {
        int k = warp * 8 + it;
        if (k < 63) {
            float acc = 0.f;
#pragma unroll
            for (int j = 0; j < 8; j++)
                acc += g_UT[k * D_ + lane + 32 * j] * smv[lane + 32 * j];
#pragma unroll
            for (int off = 16; off > 0; off >>= 1)
                acc += __shfl_down_sync(0xFFFFFFFFu, acc, off);
            if (lane == 0) zsh[k] = acc;
        }
    }
    __syncthreads();

    // weights (threads 0..63)
    float msq = 0.f;
#pragma unroll
    for (int w = 0; w < 8; w++) msq += red[w];
    if (tid == 0) {
        float sz = 0.f;
        for (int k = 0; k < 63; k++) sz += zsh[k] * zsh[k];
        w2s[0] = fmaxf(msq - sz, 0.f);           // r^2, pole 0
    } else if (tid < 64) {
        float z = zsh[tid - 1];
        w2s[tid] = z * z;
    }
    __syncthreads();

    if (tid >= 64) return;   // past the last full barrier, safe to retire

    int i = tid;
    float S = 0.f;
#pragma unroll 8
    for (int k = 0; k < NB; k++) S += w2s[k];

    float lo = ds[i];
    float hi = (i < 63) ? ds[i + 1] : ds[63] + S;
    float lam = 0.5f * (lo + hi);

    for (int it = 0; it < NIT; it++) {
        float f = 1.f, fp = 0.f;
#pragma unroll 8
        for (int k = 0; k < NB; k++) {
            float diff = ds[k] - lam;
            float rc;
            asm("rcp.approx.f32 %0, %1;" : "=f"(rc) : "f"(diff));
            float term = w2s[k] * rc;
            f  += term;
            fp += term * rc;
        }
        if (f > 0.f) hi = lam; else lo = lam;
        float ln = lam - __fdividef(f, fp);
        lam = (ln > lo && ln < hi) ? ln : 0.5f * (lo + hi);
    }

    float tr = msq + g_trA;
    float v = fmaxf(__fdividef(lam, tr), EPSV);
    vals[i] = v;
    __threadfence_block();
    asm volatile("bar.sync 1, 64;" ::: "memory");

    float ssum = 192.f * EPSV;
#pragma unroll 8
    for (int k = 0; k < NB; k++) ssum += vals[k];
    float inv = __frcp_rn(ssum);

    float* o = out + (long)t * D_;
    float ev = EPSV * inv;
    o[i]        = ev;               // positions   0..63  (zero eigs)
    o[i + 64]   = ev;               // positions  64..127
    o[i + 128]  = ev;               // positions 128..191
    o[i + 192]  = vals[i] * inv;    // positions 192..255 (roots, ascending)
}

// ---------------- launcher ----------------
extern "C" void kernel_launch(void* const* d_in, const int* in_sizes, int n_in,
                              void* d_out, int out_size) {
    const int*   tokens = (const int*)d_in[0];
    const float* embed  = (const float*)d_in[1];
    const float* bubbles= (const float*)d_in[2];
    const float* mdecay = (const float*)d_in[3];
    float* out = (float*)d_out;

    cudaFuncSetAttribute(k_eigen, cudaFuncAttributeMaxDynamicSharedMemorySize,
                         66560);

    k_setup  <<<1,    256>>>(bubbles, mdecay);
    k_gram   <<<64,   64>>>();
    k_eigen  <<<1,    1024, 66560>>>();
    k_buildU <<<63,   256>>>();
    k_gather <<<SEQ,  256>>>(tokens, embed);
    k_scan   <<<1,    256>>>();
    k_wsec   <<<SEQ,  256>>>(out);
    (void)in_sizes; (void)n_in; (void)out_size;
}

// round 7
// speedup vs baseline: 2.6249x; 1.2847x over previous
#include <cuda_runtime.h>
#include <cuda_bf16.h>
#include <math.h>

#define D_    256
#define NB    64
#define SEQ   1024
#define EPSV  1e-10f
#define NIT   12
#define NROUNDS 9          // multisection rounds, 9x contraction each

// closed-form constants
#define ALPHA     0.32768f        // (1-2*ETA)^5
#define ALPHA2_64 0.0016777216f   // ALPHA^2 / 64
#define ALPHA_8   0.04096f        // ALPHA / 8
#define BETA      0.59049f        // (1-ETA)^5
#define OMBETA    0.40951f        // 1 - BETA

// ---------------- device scratch (no allocations allowed) ----------------
__device__ float g_bm[D_];              // bubble mean
__device__ float g_D0[NB * D_];         // deviations
__device__ float g_Gg[NB * NB];         // Gram matrix
__device__ float g_Wg[NB * NB];         // eigenvectors of G (columns, ascending)
__device__ float g_UT[NB * D_];         // UT[k][d]: eigvec k of A (63 used)
__device__ float g_poles[NB];           // poles[0]=0, poles[1..63] ascending
__device__ float g_trA;                 // sum of kept poles
__device__ float g_decay;
__device__ float g_X[SEQ * D_];         // gathered embeddings
__device__ float g_M[SEQ * D_];         // m_t per step

#define BAR64() asm volatile("bar.sync 1, 64;" ::: "memory")

// ---------------- gather token embeddings (launch #1) ----------------
__global__ void k_gather(const int* __restrict__ tokens,
                         const float* __restrict__ embed) {  // <<<1024, 256>>>
    int t = blockIdx.x, d = threadIdx.x;
    g_X[t * D_ + d] = embed[(long)tokens[t] * D_ + d];
}

// ---------------- bubble mean, deviations, decay (launch #2) -------------
__global__ void k_setup(const float* __restrict__ bubbles,
                        const float* __restrict__ mdecay) {
    int d = threadIdx.x;   // 256 threads
    if (d == 0) g_decay = 1.f / (1.f + expf(-mdecay[0]));
    float s = 0.f;
#pragma unroll
    for (int i = 0; i < NB; i++) s += bubbles[i * D_ + d];
    float bm = s * (1.f / NB);
    g_bm[d] = bm;
#pragma unroll
    for (int i = 0; i < NB; i++) g_D0[i * D_ + d] = bubbles[i * D_ + d] - bm;
}

// ---------------- G = (alpha^2/64) * D0 D0^T  (launch #3) ----------------
__global__ void k_gram() {            // <<<64, 64>>>
    __shared__ float rowi[D_];
    int i = blockIdx.x, j = threadIdx.x;
    for (int dd = j; dd < D_; dd += 64) rowi[dd] = g_D0[i * D_ + dd];
    __syncthreads();
    float acc = 0.f;
#pragma unroll 4
    for (int dd = 0; dd < D_; dd++) acc += rowi[dd] * g_D0[j * D_ + dd];
    g_Gg[i * NB + j] = acc * ALPHA2_64;
}

// -- eigensolver: tridiag + multisection Sturm + invit (launch #4) --------
__global__ void k_eigen() {           // <<<1, 1024, 66560>>>
    extern __shared__ float sm[];
    float* A  = sm;                   // 64x65  (G; lower cols become v's)
    float* E  = sm + 4160;            // 64x65  (eigvec columns)
    float* DD = sm + 8320;            // 64x65  invit scratch
    float* YY = sm + 12480;           // 64x65  invit scratch

    __shared__ float diag[64], off[64], b2[64], eig[64], tauv[64];
    __shared__ float parr[64], warr[64], red[32];
    __shared__ float gl[64], gh[64];
    __shared__ int   oflag[64];
    __shared__ float sc_tau, sc_K, sc_lo, sc_hi;

    int tid = threadIdx.x, lane = tid & 31, warp = tid >> 5;

    for (int e = tid; e < NB * NB; e += 1024)
        A[(e >> 6) * 65 + (e & 63)] = g_Gg[e];
    __syncthreads();

    // ---- Householder tridiagonalization ----
    for (int k = 0; k < 62; k++) {
        int n0 = k + 1, n2 = 63 - k;
        // norm of x = A[n0..63, k]   (warps 0,1 only)
        if (tid < 64) {
            float xv = (tid < n2) ? A[(n0 + tid) * 65 + k] : 0.f;
            float s = xv * xv;
#pragma unroll
            for (int o = 16; o > 0; o >>= 1)
                s += __shfl_down_sync(0xFFFFFFFFu, s, o);
            if (lane == 0) red[warp] = s;
            BAR64();
            if (tid == 0) {
                float sum = red[0] + red[1];
                float x0 = A[n0 * 65 + k];
                float sigma = sqrtf(sum);
                float sgn = (x0 >= 0.f) ? 1.f : -1.f;
                float v0 = x0 + sgn * sigma;
                float tau = (sigma > 1e-30f)
                          ? 1.f / (sigma * (sigma + fabsf(x0))) : 0.f;
                sc_tau = tau;
                tauv[k] = tau;
                off[k] = -sgn * sigma;
                A[n0 * 65 + k] = v0;       // column k now holds v
            }
        }
        __syncthreads();
        // matvec p = tau*Asub*v : 16 threads per row
        {
            int r = tid >> 4, s16 = tid & 15;
            int rr = (r < n2) ? r : 0;
            float acc = 0.f;
            for (int c = s16; c < n2; c += 16)
                acc += A[(n0 + rr) * 65 + n0 + c] * A[(n0 + c) * 65 + k];
#pragma unroll
            for (int o = 8; o > 0; o >>= 1)
                acc += __shfl_xor_sync(0xFFFFFFFFu, acc, o, 16);
            if (r < n2 && s16 == 0) parr[r] = acc * sc_tau;
        }
        __syncthreads();
        // K = tau*(v.p)/2 ; w = p - K v   (warps 0,1)
        if (tid < 64) {
            float pv = (tid < n2) ? parr[tid] * A[(n0 + tid) * 65 + k] : 0.f;
#pragma unroll
            for (int o = 16; o > 0; o >>= 1)
                pv += __shfl_down_sync(0xFFFFFFFFu, pv, o);
            if (lane == 0) red[warp] = pv;
            BAR64();
            if (tid == 0) sc_K = 0.5f * sc_tau * (red[0] + red[1]);
            BAR64();
            if (tid < n2) warr[tid] = parr[tid] - sc_K * A[(n0 + tid) * 65 + k];
        }
        __syncthreads();
        // A_sub -= v w^T + w v^T
        for (int e = tid; e < n2 * n2; e += 1024) {
            int i = e / n2, j = e - i * n2;
            float vi = A[(n0 + i) * 65 + k];
            float vj = A[(n0 + j) * 65 + k];
            A[(n0 + i) * 65 + (n0 + j)] -= vi * warr[j] + warr[i] * vj;
        }
        __syncthreads();
    }

    if (tid < 64) diag[tid] = A[tid * 65 + tid];
    if (tid == 0) { off[62] = A[63 * 65 + 62]; off[63] = 0.f; }
    __syncthreads();
    if (tid < 63) b2[tid] = off[tid] * off[tid];
    if (tid < 64) {
        float om = (tid > 0) ? fabsf(off[tid - 1]) : 0.f;
        float op = (tid < 63) ? fabsf(off[tid]) : 0.f;
        gl[tid] = diag[tid] - om - op;
        gh[tid] = diag[tid] + om + op;
    }
    __syncthreads();
    if (tid == 0) {
        float lo = gl[0], hi = gh[0];
        for (int i = 1; i < 64; i++) {
            lo = fminf(lo, gl[i]); hi = fmaxf(hi, gh[i]);
        }
        float mg = 1e-6f * fmaxf(fabsf(lo), fabsf(hi)) + 1e-30f;
        sc_lo = lo - mg; sc_hi = hi + mg;
    }
    __syncthreads();

    // ---- multisection Sturm: 8 threads per eigenvalue (tid < 512) ----
    if (tid < 512) {
        int i = tid >> 3, s8 = tid & 7;
        float lo = sc_lo, hi = sc_hi;
        for (int round = 0; round < NROUNDS; round++) {
            float step = (hi - lo) * (1.f / 9.f);
            float mid = lo + step * (float)(s8 + 1);
            float d = diag[0] - mid;
            int cnt = (d < 0.f);
            for (int j = 1; j < 64; j++) {
                float dg = (fabsf(d) < 1e-25f) ? -1e-25f : d;
                d = (diag[j] - mid) - __fdividef(b2[j - 1], dg);
                cnt += (d < 0.f);
            }
            unsigned bal = __ballot_sync(0xFFFFFFFFu, cnt <= i);
            unsigned bits = (bal >> (lane & 24)) & 0xFFu;  // this 8-group
            int p = __popc(bits);
            float nlo = lo + step * (float)p;
            float nhi = lo + step * (float)(p + 1);
            lo = nlo; hi = nhi;
        }
        if (s8 == 0) eig[i] = 0.5f * (lo + hi);
    }
    __syncthreads();

    // ---- inverse iteration (thread i solves (T - lam I) v = b) ----
    if (tid < 64) {
        int i = tid;
        float scale = fmaxf(fabsf(sc_hi), fabsf(sc_lo));
        float lam = eig[i] + scale * 2e-6f;
        unsigned h = (unsigned)(i * 2654435761u) ^ 0x9E3779B9u;
        for (int j = 0; j < 64; j++) {
            h = h * 1664525u + 1013904223u;
            E[j * 65 + i] = 1.f + (float)(h >> 16) * 1.52587890625e-05f;
        }
        for (int iter = 0; iter < 3; iter++) {
            float dprev = diag[0] - lam;
            dprev = (fabsf(dprev) < 1e-20f) ? copysignf(1e-20f, dprev) : dprev;
            DD[i * 65 + 0] = dprev;
            float yprev = E[0 * 65 + i];
            YY[i * 65 + 0] = yprev;
            for (int j = 1; j < 64; j++) {
                float m = __fdividef(off[j - 1], dprev);
                float dcur = (diag[j] - lam) - m * off[j - 1];
                dcur = (fabsf(dcur) < 1e-20f) ? copysignf(1e-20f, dcur) : dcur;
                float ycur = E[j * 65 + i] - m * yprev;
                DD[i * 65 + j] = dcur;
                YY[i * 65 + j] = ycur;
                dprev = dcur; yprev = ycur;
            }
            float vj = __fdividef(YY[i * 65 + 63], DD[i * 65 + 63]);
            E[63 * 65 + i] = vj;
            float nrm = vj * vj;
            for (int j = 62; j >= 0; j--) {
                vj = __fdividef(YY[i * 65 + j] - off[j] * vj, DD[i * 65 + j]);
                E[j * 65 + i] = vj;
                nrm += vj * vj;
            }
            float inv = rsqrtf(nrm);
            for (int j = 0; j < 64; j++) E[j * 65 + i] *= inv;
        }
    }
    __syncthreads();

    // ---- gap-flagged neighbor re-orthogonalization ----
    if (tid < 64) {
        float scale = fmaxf(fabsf(eig[63]), fabsf(eig[0]));
        oflag[tid] = (tid > 0) && (eig[tid] - eig[tid - 1] < 1e-3f * scale);
    }
    __syncthreads();
    for (int i = 1; i < 64; i++) {
        if (!oflag[i]) continue;
        float pr = (tid < 64) ? E[tid * 65 + i] * E[tid * 65 + i - 1] : 0.f;
#pragma unroll
        for (int o = 16; o > 0; o >>= 1)
            pr += __shfl_down_sync(0xFFFFFFFFu, pr, o);
        if (lane == 0 && tid < 64) red[warp] = pr;
        __syncthreads();
        float dot = red[0] + red[1];
        float nv = 0.f;
        if (tid < 64) {
            E[tid * 65 + i] -= dot * E[tid * 65 + i - 1];
            nv = E[tid * 65 + i] * E[tid * 65 + i];
        }
#pragma unroll
        for (int o = 16; o > 0; o >>= 1)
            nv += __shfl_down_sync(0xFFFFFFFFu, nv, o);
        if (lane == 0 && tid < 64) red[warp] = nv;
        __syncthreads();
        float sc = rsqrtf(red[0] + red[1] + 1e-30f);
        if (tid < 64) E[tid * 65 + i] *= sc;
        __syncthreads();
    }

    // ---- back-transform: apply reflectors k = 61..0 (cols independent) ----
    {
        int col = tid >> 4, sub = tid & 15;
        for (int k = 61; k >= 0; k--) {
            int n0 = k + 1, n2 = 63 - k;
            float tau = tauv[k];
            float acc = 0.f;
            for (int r = sub; r < n2; r += 16)
                acc += A[(n0 + r) * 65 + k] * E[(n0 + r) * 65 + col];
#pragma unroll
            for (int o = 8; o > 0; o >>= 1)
                acc += __shfl_xor_sync(0xFFFFFFFFu, acc, o, 16);
            float w = tau * acc;
            for (int r = sub; r < n2; r += 16)
                E[(n0 + r) * 65 + col] -= w * A[(n0 + r) * 65 + k];
            // no barrier: each 16-thread group touches only its own column
        }
    }
    __syncthreads();

    // ---- publish: poles ascending (drop index 0 = null mode) ----
    if (tid == 0) {
        g_poles[0] = 0.f;
        float s = 0.f;
        for (int k = 1; k < 64; k++) {
            float p = fmaxf(eig[k], 1e-12f);
            g_poles[k] = p;
            s += p;
        }
        g_trA = s;
    }
    for (int e = tid; e < NB * NB; e += 1024)
        g_Wg[e] = E[(e >> 6) * 65 + (e & 63)];
}

// ---------------- build U^T (launch #5) ----------------
__global__ void k_buildU() {          // <<<63, 256>>>
    __shared__ float wcol[NB];
    int k = blockIdx.x, d = threadIdx.x;
    if (d < NB) wcol[d] = g_Wg[d * NB + (k + 1)];   // ascending columns
    __syncthreads();
    float acc = 0.f;
#pragma unroll 8
    for (int i = 0; i < NB; i++) acc += g_D0[i * D_ + d] * wcol[i];
    float lam = g_poles[k + 1];
    g_UT[k * D_ + d] = acc * ALPHA_8 * rsqrtf(fmaxf(lam, 1e-20f));
}

// -------- parallel memory scan: mm_t = a*mm + b_t, a^96 ~ 3e-11 ----------
__global__ void k_scan() {            // <<<16, 256>>>
    int c = blockIdx.x, d = threadIdx.x;
    float decay = g_decay;
    float omdecay = 1.f - decay;
    float cb = BETA * g_bm[d];
    int tout = c * 64;
    int tstart = tout - 96; if (tstart < 0) tstart = 0;
    int tend = tout + 64;
    float mm = 0.f;
    float xs[8];
#pragma unroll
    for (int j = 0; j < 8; j++) xs[j] = g_X[(tstart + j) * D_ + d];
    for (int t0 = tstart; t0 < tend; t0 += 8) {
#pragma unroll
        for (int j = 0; j < 8; j++) {
            int t = t0 + j;
            float x = xs[j];
            int tn = t0 + 8 + j;
            if (tn < tend) xs[j] = g_X[tn * D_ + d];
            float m = cb + OMBETA * (x + decay * mm);
            if (t >= tout) g_M[t * D_ + d] = m;
            mm = decay * mm + omdecay * m;
        }
    }
}

// ---------------- fused weights + secular roots + output -----------------
__global__ void k_wsec(float* __restrict__ out) {  // <<<1024, 256>>>
    __shared__ float smv[D_];
    __shared__ float zsh[64];
    __shared__ float red[8];
    __shared__ float w2s[NB], ds[NB], vals[NB];
    int t = blockIdx.x, tid = threadIdx.x;
    int warp = tid >> 5, lane = tid & 31;

    float mv = g_M[t * D_ + tid];
    smv[tid] = mv;
    float p = mv * mv;
#pragma unroll
    for (int off = 16; off > 0; off >>= 1)
        p += __shfl_down_sync(0xFFFFFFFFu, p, off);
    if (lane == 0) red[warp] = p;
    if (tid < NB) ds[tid] = g_poles[tid];
    __syncthreads();

    // z_k = U_k . m  for k = 0..62 (warp-per-k, 8 per warp)
#pragma unroll
    for (int it = 0; it < 8; it++) {
        int k = warp * 8 + it;
        if (k < 63) {
            float acc = 0.f;
#pragma unroll
            for (int j = 0; j < 8; j++)
                acc += g_UT[k * D_ + lane + 32 * j] * smv[lane + 32 * j];
#pragma unroll
            for (int off = 16; off > 0; off >>= 1)
                acc += __shfl_down_sync(0xFFFFFFFFu, acc, off);
            if (lane == 0) zsh[k] = acc;
        }
    }
    __syncthreads();

    // weights (threads 0..63)
    float msq = 0.f;
#pragma unroll
    for (int w = 0; w < 8; w++) msq += red[w];
    if (tid == 0) {
        float sz = 0.f;
        for (int k = 0; k < 63; k++) sz += zsh[k] * zsh[k];
        w2s[0] = fmaxf(msq - sz, 0.f);           // r^2, pole 0
    } else if (tid < 64) {
        float z = zsh[tid - 1];
        w2s[tid] = z * z;
    }
    __syncthreads();

    if (tid >= 64) return;   // past the last full barrier, safe to retire

    int i = tid;
    float S = 0.f;
#pragma unroll 8
    for (int k = 0; k < NB; k++) S += w2s[k];

    float lo = ds[i];
    float hi = (i < 63) ? ds[i + 1] : ds[63] + S;
    float lam = 0.5f * (lo + hi);

    for (int it = 0; it < NIT; it++) {
        float f = 1.f, fp = 0.f;
#pragma unroll 8
        for (int k = 0; k < NB; k++) {
            float diff = ds[k] - lam;
            float rc;
            asm("rcp.approx.f32 %0, %1;" : "=f"(rc) : "f"(diff));
            float term = w2s[k] * rc;
            f  += term;
            fp += term * rc;
        }
        if (f > 0.f) hi = lam; else lo = lam;
        float ln = lam - __fdividef(f, fp);
        lam = (ln > lo && ln < hi) ? ln : 0.5f * (lo + hi);
    }

    float tr = msq + g_trA;
    float v = fmaxf(__fdividef(lam, tr), EPSV);
    vals[i] = v;
    __threadfence_block();
    asm volatile("bar.sync 1, 64;" ::: "memory");

    float ssum = 192.f * EPSV;
#pragma unroll 8
    for (int k = 0; k < NB; k++) ssum += vals[k];
    float inv = __frcp_rn(ssum);

    float* o = out + (long)t * D_;
    float ev = EPSV * inv;
    o[i]        = ev;               // positions   0..63  (zero eigs)
    o[i + 64]   = ev;               // positions  64..127
    o[i + 128]  = ev;               // positions 128..191
    o[i + 192]  = vals[i] * inv;    // positions 192..255 (roots, ascending)
}

// ---------------- launcher ----------------
extern "C" void kernel_launch(void* const* d_in, const int* in_sizes, int n_in,
                              void* d_out, int out_size) {
    const int*   tokens = (const int*)d_in[0];
    const float* embed  = (const float*)d_in[1];
    const float* bubbles= (const float*)d_in[2];
    const float* mdecay = (const float*)d_in[3];
    float* out = (float*)d_out;

    cudaFuncSetAttribute(k_eigen, cudaFuncAttributeMaxDynamicSharedMemorySize,
                         66560);

    k_gather <<<SEQ,  256>>>(tokens, embed);
    k_setup  <<<1,    256>>>(bubbles, mdecay);
    k_gram   <<<64,   64>>>();
    k_eigen  <<<1,    1024, 66560>>>();
    k_buildU <<<63,   256>>>();
    k_scan   <<<16,   256>>>();
    k_wsec   <<<SEQ,  256>>>(out);
    (void)in_sizes; (void)n_in; (void)out_size;
}

// round 8
// speedup vs baseline: 3.1712x; 1.2081x over previous
#include <cuda_runtime.h>
#include <cuda_bf16.h>
#include <math.h>

#define D_    256
#define NB    64
#define SEQ   1024
#define EPSV  1e-10f
#define NIT   12
#define NROUNDS 9          // multisection rounds, 9x contraction each

// closed-form constants
#define ALPHA     0.32768f        // (1-2*ETA)^5
#define ALPHA2_64 0.0016777216f   // ALPHA^2 / 64
#define ALPHA_8   0.04096f        // ALPHA / 8
#define BETA      0.59049f        // (1-ETA)^5
#define OMBETA    0.40951f        // 1 - BETA

// ---------------- device scratch (no allocations allowed) ----------------
__device__ float g_bm[D_];              // bubble mean
__device__ float g_D0[NB * D_];         // deviations
__device__ float g_Gg[NB * NB];         // Gram matrix
__device__ float g_V[62 * NB];          // Householder reflectors v (per step)
__device__ float g_tau[64];             // reflector taus
__device__ float g_diag[NB];            // tridiag diagonal
__device__ float g_off[NB];             // tridiag off-diagonal
__device__ float g_Wg[NB * NB];         // eigenvectors of G (columns, ascending)
__device__ float g_UT[NB * D_];         // UT[k][d]: eigvec k of A (63 used)
__device__ float g_poles[NB];           // poles[0]=0, poles[1..63] ascending
__device__ float g_trA;                 // sum of kept poles
__device__ float g_decay;
__device__ float g_M[SEQ * D_];         // m_t per step

// ------ 1) fused setup + Gram: G = (a^2/64) D0 D0^T  <<<64,64>>> ---------
__global__ void k_gramsetup(const float* __restrict__ bubbles,
                            const float* __restrict__ mdecay) {
    __shared__ float bmsh[D_];
    __shared__ float rowi[D_];
    int i = blockIdx.x, j = threadIdx.x;   // 64 threads

    // bubble mean (computed redundantly per block; L2-hot)
    float s0 = 0.f, s1 = 0.f, s2 = 0.f, s3 = 0.f;
    for (int r = 0; r < NB; r++) {
        const float* br = bubbles + r * D_;
        s0 += br[j]; s1 += br[j + 64]; s2 += br[j + 128]; s3 += br[j + 192];
    }
    bmsh[j]       = s0 * (1.f / NB);
    bmsh[j + 64]  = s1 * (1.f / NB);
    bmsh[j + 128] = s2 * (1.f / NB);
    bmsh[j + 192] = s3 * (1.f / NB);
    __syncthreads();

    // D0 row i into smem + writeback
    for (int dd = j; dd < D_; dd += 64) {
        float v = bubbles[i * D_ + dd] - bmsh[dd];
        rowi[dd] = v;
        g_D0[i * D_ + dd] = v;
    }
    if (i == 0) {
        for (int dd = j; dd < D_; dd += 64) g_bm[dd] = bmsh[dd];
        if (j == 0) g_decay = 1.f / (1.f + expf(-mdecay[0]));
    }
    __syncthreads();

    // Gram element (i, j)
    float acc = 0.f;
    const float* bj = bubbles + j * D_;
#pragma unroll 4
    for (int dd = 0; dd < D_; dd++)
        acc += rowi[dd] * (bj[dd] - bmsh[dd]);
    g_Gg[i * NB + j] = acc * ALPHA2_64;
}

// ------ 2) register-resident Householder tridiagonalization <<<1,64>>> ---
__global__ void __launch_bounds__(64) k_tridiag() {
    __shared__ float vsh[NB], wsh[NB], red2[2];
    __shared__ float x0sh;
    float row[NB];
    int r = threadIdx.x, lane = r & 31, warp = r >> 5;

#pragma unroll
    for (int c = 0; c < NB; c++) row[c] = g_Gg[r * NB + c];
    float x = row[0];

#pragma unroll 1
    for (int k = 0; k < 62; k++) {
        int n0 = k + 1;
        float xm = (r >= n0) ? x : 0.f;
        float s = xm * xm;
#pragma unroll
        for (int o = 16; o > 0; o >>= 1) s += __shfl_xor_sync(0xFFFFFFFFu, s, o);
        if (lane == 0) red2[warp] = s;
        if (r == n0) x0sh = xm;
        __syncthreads();
        float sum = red2[0] + red2[1];
        float x0 = x0sh;
        float sigma = sqrtf(sum);
        float sgn = (x0 >= 0.f) ? 1.f : -1.f;
        float tau = (sum > 1e-30f)
                  ? __fdividef(1.f, sigma * (sigma + fabsf(x0))) : 0.f;
        if (r == 0) { g_off[k] = -sgn * sigma; g_tau[k] = tau; }
        float v = (r == n0) ? x0 + sgn * sigma : xm;   // xm==0 for r<n0
        vsh[r] = v;
        g_V[k * NB + r] = v;
        __syncthreads();
        // p = tau * row . v   (4-way accumulators)
        float a0 = 0.f, a1 = 0.f, a2 = 0.f, a3 = 0.f;
#pragma unroll
        for (int c = 0; c < NB; c += 4) {
            a0 += row[c]     * vsh[c];
            a1 += row[c + 1] * vsh[c + 1];
            a2 += row[c + 2] * vsh[c + 2];
            a3 += row[c + 3] * vsh[c + 3];
        }
        float p = tau * ((a0 + a1) + (a2 + a3));
        float pv = p * v;
#pragma unroll
        for (int o = 16; o > 0; o >>= 1) pv += __shfl_xor_sync(0xFFFFFFFFu, pv, o);
        if (lane == 0) red2[warp] = pv;
        __syncthreads();
        float K = 0.5f * tau * (red2[0] + red2[1]);
        float w = (r >= n0) ? (p - K * v) : 0.f;
        wsh[r] = w;
        __syncthreads();
        // row update + predicated capture of next x = A[r][k+1]
        float xn = x;
#pragma unroll
        for (int c = 0; c < NB; c++) {
            float nv = row[c] - v * wsh[c] - w * vsh[c];
            row[c] = nv;
            if (c == n0) xn = nv;
        }
        x = xn;
    }

    // publish diag (predicated capture), off tail
    float dg = 0.f;
#pragma unroll
    for (int c = 0; c < NB; c++) if (c == r) dg = row[c];
    g_diag[r] = dg;
    if (r == 63) g_off[62] = row[62];
    if (r == 0)  g_off[63] = 0.f;
}

// ------ 3) eigvecs: multisection Sturm + invit + backtransform -----------
__global__ void k_eigvec() {          // <<<1, 1024, 66560>>>
    extern __shared__ float sm[];
    float* E  = sm;                   // 64x65 eigvec columns
    float* DD = sm + 4160;            // invit scratch
    float* YY = sm + 8320;            // invit scratch
    float* V  = sm + 12480;           // reflectors [k][r], pitch 65

    __shared__ float diag[64], off[64], b2[64], eig[64], tauv[64];
    __shared__ float red[32];
    __shared__ int   oflag[64];
    __shared__ float sc_lo, sc_hi;

    int tid = threadIdx.x, lane = tid & 31, warp = tid >> 5;

    if (tid < 64) { diag[tid] = g_diag[tid]; off[tid] = g_off[tid]; }
    if (tid < 62) tauv[tid] = g_tau[tid];
    for (int e = tid; e < 62 * NB; e += 1024)
        V[(e >> 6) * 65 + (e & 63)] = g_V[e];
    __syncthreads();
    if (tid < 63) b2[tid] = off[tid] * off[tid];
    if (tid == 0) {
        float lo = 1e30f, hi = -1e30f;
        for (int i = 0; i < 64; i++) {
            float om = (i > 0) ? fabsf(off[i - 1]) : 0.f;
            float op = (i < 63) ? fabsf(off[i]) : 0.f;
            lo = fminf(lo, diag[i] - om - op);
            hi = fmaxf(hi, diag[i] + om + op);
        }
        float mg = 1e-6f * fmaxf(fabsf(lo), fabsf(hi)) + 1e-30f;
        sc_lo = lo - mg; sc_hi = hi + mg;
    }
    __syncthreads();

    // ---- multisection Sturm: 8 threads per eigenvalue ----
    if (tid < 512) {
        int i = tid >> 3, s8 = tid & 7;
        float lo = sc_lo, hi = sc_hi;
        for (int round = 0; round < NROUNDS; round++) {
            float step = (hi - lo) * (1.f / 9.f);
            float mid = lo + step * (float)(s8 + 1);
            float d = diag[0] - mid;
            int cnt = (d < 0.f);
            for (int j = 1; j < 64; j++) {
                float dg = (fabsf(d) < 1e-25f) ? -1e-25f : d;
                d = (diag[j] - mid) - __fdividef(b2[j - 1], dg);
                cnt += (d < 0.f);
            }
            unsigned bal = __ballot_sync(0xFFFFFFFFu, cnt <= i);
            unsigned bits = (bal >> (lane & 24)) & 0xFFu;
            int p = __popc(bits);
            lo = lo + step * (float)p;
            hi = lo + step;
        }
        if (s8 == 0) eig[i] = 0.5f * (lo + hi);
    }
    __syncthreads();

    // ---- inverse iteration ----
    if (tid < 64) {
        int i = tid;
        float scale = fmaxf(fabsf(sc_hi), fabsf(sc_lo));
        float lam = eig[i] + scale * 2e-6f;
        unsigned h = (unsigned)(i * 2654435761u) ^ 0x9E3779B9u;
        for (int j = 0; j < 64; j++) {
            h = h * 1664525u + 1013904223u;
            E[j * 65 + i] = 1.f + (float)(h >> 16) * 1.52587890625e-05f;
        }
        for (int iter = 0; iter < 3; iter++) {
            float dprev = diag[0] - lam;
            dprev = (fabsf(dprev) < 1e-20f) ? copysignf(1e-20f, dprev) : dprev;
            DD[i * 65 + 0] = dprev;
            float yprev = E[0 * 65 + i];
            YY[i * 65 + 0] = yprev;
            for (int j = 1; j < 64; j++) {
                float m = __fdividef(off[j - 1], dprev);
                float dcur = (diag[j] - lam) - m * off[j - 1];
                dcur = (fabsf(dcur) < 1e-20f) ? copysignf(1e-20f, dcur) : dcur;
                float ycur = E[j * 65 + i] - m * yprev;
                DD[i * 65 + j] = dcur;
                YY[i * 65 + j] = ycur;
                dprev = dcur; yprev = ycur;
            }
            float vj = __fdividef(YY[i * 65 + 63], DD[i * 65 + 63]);
            E[63 * 65 + i] = vj;
            float nrm = vj * vj;
            for (int j = 62; j >= 0; j--) {
                vj = __fdividef(YY[i * 65 + j] - off[j] * vj, DD[i * 65 + j]);
                E[j * 65 + i] = vj;
                nrm += vj * vj;
            }
            float inv = rsqrtf(nrm);
            for (int j = 0; j < 64; j++) E[j * 65 + i] *= inv;
        }
    }
    __syncthreads();

    // ---- gap-flagged neighbor re-orthogonalization ----
    if (tid < 64) {
        float scale = fmaxf(fabsf(eig[63]), fabsf(eig[0]));
        oflag[tid] = (tid > 0) && (eig[tid] - eig[tid - 1] < 1e-3f * scale);
    }
    __syncthreads();
    for (int i = 1; i < 64; i++) {
        if (!oflag[i]) continue;
        float pr = (tid < 64) ? E[tid * 65 + i] * E[tid * 65 + i - 1] : 0.f;
#pragma unroll
        for (int o = 16; o > 0; o >>= 1)
            pr += __shfl_down_sync(0xFFFFFFFFu, pr, o);
        if (lane == 0 && tid < 64) red[warp] = pr;
        __syncthreads();
        float dot = red[0] + red[1];
        float nv = 0.f;
        if (tid < 64) {
            E[tid * 65 + i] -= dot * E[tid * 65 + i - 1];
            nv = E[tid * 65 + i] * E[tid * 65 + i];
        }
#pragma unroll
        for (int o = 16; o > 0; o >>= 1)
            nv += __shfl_down_sync(0xFFFFFFFFu, nv, o);
        if (lane == 0 && tid < 64) red[warp] = nv;
        __syncthreads();
        float sc = rsqrtf(red[0] + red[1] + 1e-30f);
        if (tid < 64) E[tid * 65 + i] *= sc;
        __syncthreads();
    }

    // ---- back-transform: apply reflectors k = 61..0 (cols independent) --
    {
        int col = tid >> 4, sub = tid & 15;
        for (int k = 61; k >= 0; k--) {
            int n0 = k + 1, n2 = 63 - k;
            float tau = tauv[k];
            float acc = 0.f;
            for (int r = sub; r < n2; r += 16)
                acc += V[k * 65 + n0 + r] * E[(n0 + r) * 65 + col];
#pragma unroll
            for (int o = 8; o > 0; o >>= 1)
                acc += __shfl_xor_sync(0xFFFFFFFFu, acc, o, 16);
            float w = tau * acc;
            for (int r = sub; r < n2; r += 16)
                E[(n0 + r) * 65 + col] -= w * V[k * 65 + n0 + r];
        }
    }
    __syncthreads();

    // ---- publish: poles ascending (drop index 0 = null mode) ----
    if (tid == 0) {
        g_poles[0] = 0.f;
        float s = 0.f;
        for (int k = 1; k < 64; k++) {
            float p = fmaxf(eig[k], 1e-12f);
            g_poles[k] = p;
            s += p;
        }
        g_trA = s;
    }
    for (int e = tid; e < NB * NB; e += 1024)
        g_Wg[e] = E[(e >> 6) * 65 + (e & 63)];
}

// ---------------- 4) build U^T ----------------
__global__ void k_buildU() {          // <<<63, 256>>>
    __shared__ float wcol[NB];
    int k = blockIdx.x, d = threadIdx.x;
    if (d < NB) wcol[d] = g_Wg[d * NB + (k + 1)];   // ascending columns
    __syncthreads();
    float acc = 0.f;
#pragma unroll 8
    for (int i = 0; i < NB; i++) acc += g_D0[i * D_ + d] * wcol[i];
    float lam = g_poles[k + 1];
    g_UT[k * D_ + d] = acc * ALPHA_8 * rsqrtf(fmaxf(lam, 1e-20f));
}

// ------ 5) memory scan with inline gather (a^96 ~ 3e-11 warmup) ----------
__global__ void k_scan(const int* __restrict__ tokens,
                       const float* __restrict__ embed) {  // <<<16, 256>>>
    __shared__ int tk[160];
    int c = blockIdx.x, d = threadIdx.x;
    int tout = c * 64;
    int tstart = tout - 96; if (tstart < 0) tstart = 0;
    int tend = tout + 64;
    int nwin = tend - tstart;
    if (d < nwin) tk[d] = tokens[tstart + d];
    __syncthreads();

    float decay = g_decay;
    float omdecay = 1.f - decay;
    float cb = BETA * g_bm[d];
    float mm = 0.f;
    float xs[8];
#pragma unroll
    for (int j = 0; j < 8; j++) xs[j] = embed[(long)tk[j] * D_ + d];
    for (int t0 = tstart; t0 < tend; t0 += 8) {
#pragma unroll
        for (int j = 0; j < 8; j++) {
            int t = t0 + j;
            float x = xs[j];
            int tn = t0 + 8 + j;
            if (tn < tend) xs[j] = embed[(long)tk[tn - tstart] * D_ + d];
            float m = cb + OMBETA * (x + decay * mm);
            if (t >= tout) g_M[t * D_ + d] = m;
            mm = decay * mm + omdecay * m;
        }
    }
}

// ---------------- 6) fused weights + secular roots + output --------------
__global__ void k_wsec(float* __restrict__ out) {  // <<<1024, 256>>>
    __shared__ float smv[D_];
    __shared__ float zsh[64];
    __shared__ float red[8];
    __shared__ float w2s[NB], ds[NB], vals[NB];
    int t = blockIdx.x, tid = threadIdx.x;
    int warp = tid >> 5, lane = tid & 31;

    float mv = g_M[t * D_ + tid];
    smv[tid] = mv;
    float p = mv * mv;
#pragma unroll
    for (int off = 16; off > 0; off >>= 1)
        p += __shfl_down_sync(0xFFFFFFFFu, p, off);
    if (lane == 0) red[warp] = p;
    if (tid < NB) ds[tid] = g_poles[tid];
    __syncthreads();

    // z_k = U_k . m  for k = 0..62 (warp-per-k, 8 per warp)
#pragma unroll
    for (int it = 0; it < 8; it++) {
        int k = warp * 8 + it;
        if (k < 63) {
            float acc = 0.f;
#pragma unroll
            for (int j = 0; j < 8; j++)
                acc += g_UT[k * D_ + lane + 32 * j] * smv[lane + 32 * j];
#pragma unroll
            for (int off = 16; off > 0; off >>= 1)
                acc += __shfl_down_sync(0xFFFFFFFFu, acc, off);
            if (lane == 0) zsh[k] = acc;
        }
    }
    __syncthreads();

    float msq = 0.f;
#pragma unroll
    for (int w = 0; w < 8; w++) msq += red[w];
    if (tid == 0) {
        float sz = 0.f;
        for (int k = 0; k < 63; k++) sz += zsh[k] * zsh[k];
        w2s[0] = fmaxf(msq - sz, 0.f);           // r^2, pole 0
    } else if (tid < 64) {
        float z = zsh[tid - 1];
        w2s[tid] = z * z;
    }
    __syncthreads();

    if (tid >= 64) return;   // past the last full barrier, safe to retire

    int i = tid;
    float S = 0.f;
#pragma unroll 8
    for (int k = 0; k < NB; k++) S += w2s[k];

    float lo = ds[i];
    float hi = (i < 63) ? ds[i + 1] : ds[63] + S;
    float lam = 0.5f * (lo + hi);

    for (int it = 0; it < NIT; it++) {
        float f = 1.f, fp = 0.f;
#pragma unroll 8
        for (int k = 0; k < NB; k++) {
            float diff = ds[k] - lam;
            float rc;
            asm("rcp.approx.f32 %0, %1;" : "=f"(rc) : "f"(diff));
            float term = w2s[k] * rc;
            f  += term;
            fp += term * rc;
        }
        if (f > 0.f) hi = lam; else lo = lam;
        float ln = lam - __fdividef(f, fp);
        lam = (ln > lo && ln < hi) ? ln : 0.5f * (lo + hi);
    }

    float tr = msq + g_trA;
    float v = fmaxf(__fdividef(lam, tr), EPSV);
    vals[i] = v;
    __threadfence_block();
    asm volatile("bar.sync 1, 64;" ::: "memory");

    float ssum = 192.f * EPSV;
#pragma unroll 8
    for (int k = 0; k < NB; k++) ssum += vals[k];
    float inv = __frcp_rn(ssum);

    float* o = out + (long)t * D_;
    float ev = EPSV * inv;
    o[i]        = ev;               // positions   0..63  (zero eigs)
    o[i + 64]   = ev;               // positions  64..127
    o[i + 128]  = ev;               // positions 128..191
    o[i + 192]  = vals[i] * inv;    // positions 192..255 (roots, ascending)
}

// ---------------- launcher ----------------
extern "C" void kernel_launch(void* const* d_in, const int* in_sizes, int n_in,
                              void* d_out, int out_size) {
    const int*   tokens = (const int*)d_in[0];
    const float* embed  = (const float*)d_in[1];
    const float* bubbles= (const float*)d_in[2];
    const float* mdecay = (const float*)d_in[3];
    float* out = (float*)d_out;

    cudaFuncSetAttribute(k_eigvec, cudaFuncAttributeMaxDynamicSharedMemorySize,
                         66560);

    k_gramsetup<<<64, 64>>>(bubbles, mdecay);
    k_tridiag  <<<1, 64>>>();
    k_eigvec   <<<1, 1024, 66560>>>();
    k_buildU   <<<63, 256>>>();
    k_scan     <<<16, 256>>>(tokens, embed);
    k_wsec     <<<SEQ, 256>>>(out);
    (void)in_sizes; (void)n_in; (void)out_size;
}

// round 10
// speedup vs baseline: 3.1816x; 1.0033x over previous
#include <cuda_runtime.h>
#include <cuda_bf16.h>
#include <math.h>

#define D_    256
#define NB    64
#define SEQ   1024
#define EPSV  1e-10f
#define NIT   12
#define NROUNDS 9          // multisection rounds, 9x contraction each

// closed-form constants
#define ALPHA     0.32768f        // (1-2*ETA)^5
#define ALPHA2_64 0.0016777216f   // ALPHA^2 / 64
#define ALPHA_8   0.04096f        // ALPHA / 8
#define BETA      0.59049f        // (1-ETA)^5
#define OMBETA    0.40951f        // 1 - BETA

// ---------------- device scratch (no allocations allowed) ----------------
__device__ float g_D0[NB * D_];         // deviations
__device__ float g_Gg[NB * NB];         // Gram matrix
__device__ float g_V[62 * NB];          // Householder reflectors v (per step)
__device__ float g_tau[64];             // reflector taus
__device__ float g_diag[NB];            // tridiag diagonal
__device__ float g_off[NB];             // tridiag off-diagonal
__device__ float g_Wg[NB * NB];         // eigenvectors of G (columns, ascending)
__device__ float g_UT[NB * D_];         // UT[k][d]: eigvec k of A (63 used)
__device__ float g_poles[NB];           // poles[0]=0, poles[1..63] ascending
__device__ float g_trA;                 // sum of kept poles
__device__ float g_M[SEQ * D_];         // m_t per step

// ------ 1) memory scan, self-sufficient  <<<32,256>>> --------------------
// contraction a = decay*(1+(1-decay)*OMBETA) ~ 0.778; a^96 ~ 3e-11
__global__ void k_scan(const int* __restrict__ tokens,
                       const float* __restrict__ embed,
                       const float* __restrict__ bubbles,
                       const float* __restrict__ mdecay) {
    __shared__ int tk[128];
    int c = blockIdx.x, d = threadIdx.x;

    // bubble-mean component d (redundant per block; L2-hot)
    float s0 = 0.f, s1 = 0.f;
#pragma unroll 8
    for (int r = 0; r < NB; r += 2) {
        s0 += bubbles[r * D_ + d];
        s1 += bubbles[(r + 1) * D_ + d];
    }
    float cb = BETA * (s0 + s1) * (1.f / NB);
    float decay = 1.f / (1.f + expf(-mdecay[0]));
    float omdecay = 1.f - decay;

    int tout = c * 32;
    int tstart = tout - 96; if (tstart < 0) tstart = 0;
    int tend = tout + 32;
    int nwin = tend - tstart;
    if (d < nwin) tk[d] = tokens[tstart + d];
    __syncthreads();

    float mm = 0.f;
    float xs[8];
#pragma unroll
    for (int j = 0; j < 8; j++) xs[j] = embed[(long)tk[j] * D_ + d];
    for (int t0 = tstart; t0 < tend; t0 += 8) {
#pragma unroll
        for (int j = 0; j < 8; j++) {
            int t = t0 + j;
            float x = xs[j];
            int tn = t0 + 8 + j;
            if (tn < tend) xs[j] = embed[(long)tk[tn - tstart] * D_ + d];
            float m = cb + OMBETA * (x + decay * mm);
            if (t >= tout) g_M[t * D_ + d] = m;
            mm = decay * mm + omdecay * m;
        }
    }
}

// ------ 2) setup + Gram: G = (a^2/64) D0 D0^T  <<<64,64>>> ---------------
__global__ void k_gramsetup(const float* __restrict__ bubbles) {
    __shared__ float bmsh[D_];
    __shared__ float rowi[D_];
    int i = blockIdx.x, j = threadIdx.x;   // 64 threads

    float s0 = 0.f, s1 = 0.f, s2 = 0.f, s3 = 0.f;
#pragma unroll 4
    for (int r = 0; r < NB; r++) {
        const float* br = bubbles + r * D_;
        s0 += br[j]; s1 += br[j + 64]; s2 += br[j + 128]; s3 += br[j + 192];
    }
    bmsh[j]       = s0 * (1.f / NB);
    bmsh[j + 64]  = s1 * (1.f / NB);
    bmsh[j + 128] = s2 * (1.f / NB);
    bmsh[j + 192] = s3 * (1.f / NB);
    __syncthreads();

    for (int dd = j; dd < D_; dd += 64) {
        float v = bubbles[i * D_ + dd] - bmsh[dd];
        rowi[dd] = v;
        g_D0[i * D_ + dd] = v;
    }
    __syncthreads();

    float acc = 0.f;
    const float* bj = bubbles + j * D_;
#pragma unroll 8
    for (int dd = 0; dd < D_; dd++)
        acc += rowi[dd] * (bj[dd] - bmsh[dd]);
    g_Gg[i * NB + j] = acc * ALPHA2_64;
}

// ------ 3) register-resident Householder tridiagonalization <<<1,64>>> ---
__global__ void __launch_bounds__(64) k_tridiag() {
    __shared__ float vsh[NB], wsh[NB], red2[2];
    __shared__ float x0sh;
    float row[NB];
    int r = threadIdx.x, lane = r & 31, warp = r >> 5;

#pragma unroll
    for (int c = 0; c < NB; c++) row[c] = g_Gg[r * NB + c];
    float x = row[0];

#pragma unroll 1
    for (int k = 0; k < 62; k++) {
        int n0 = k + 1;
        float xm = (r >= n0) ? x : 0.f;
        float s = xm * xm;
#pragma unroll
        for (int o = 16; o > 0; o >>= 1) s += __shfl_xor_sync(0xFFFFFFFFu, s, o);
        if (lane == 0) red2[warp] = s;
        if (r == n0) x0sh = xm;
        __syncthreads();
        float sum = red2[0] + red2[1];
        float x0 = x0sh;
        float sigma = sqrtf(sum);
        float sgn = (x0 >= 0.f) ? 1.f : -1.f;
        float tau = (sum > 1e-30f)
                  ? __fdividef(1.f, sigma * (sigma + fabsf(x0))) : 0.f;
        if (r == 0) { g_off[k] = -sgn * sigma; g_tau[k] = tau; }
        float v = (r == n0) ? x0 + sgn * sigma : xm;   // xm==0 for r<n0
        vsh[r] = v;
        g_V[k * NB + r] = v;
        __syncthreads();
        float a0 = 0.f, a1 = 0.f, a2 = 0.f, a3 = 0.f;
#pragma unroll
        for (int c = 0; c < NB; c += 4) {
            a0 += row[c]     * vsh[c];
            a1 += row[c + 1] * vsh[c + 1];
            a2 += row[c + 2] * vsh[c + 2];
            a3 += row[c + 3] * vsh[c + 3];
        }
        float p = tau * ((a0 + a1) + (a2 + a3));
        float pv = p * v;
#pragma unroll
        for (int o = 16; o > 0; o >>= 1) pv += __shfl_xor_sync(0xFFFFFFFFu, pv, o);
        if (lane == 0) red2[warp] = pv;
        __syncthreads();
        float K = 0.5f * tau * (red2[0] + red2[1]);
        float w = (r >= n0) ? (p - K * v) : 0.f;
        wsh[r] = w;
        __syncthreads();
        float xn = x;
#pragma unroll
        for (int c = 0; c < NB; c++) {
            float nv = row[c] - v * wsh[c] - w * vsh[c];
            row[c] = nv;
            if (c == n0) xn = nv;
        }
        x = xn;
    }

    float dg = 0.f;
#pragma unroll
    for (int c = 0; c < NB; c++) if (c == r) dg = row[c];
    g_diag[r] = dg;
    if (r == 63) g_off[62] = row[62];
    if (r == 0)  g_off[63] = 0.f;
}

// ------ 4) eigvecs: multisection Sturm + invit + backtransform -----------
__global__ void k_eigvec() {          // <<<1, 1024, 66560>>>
    extern __shared__ float sm[];
    float* E  = sm;                   // 64x65 eigvec columns
    float* DD = sm + 4160;            // invit scratch
    float* YY = sm + 8320;            // invit scratch
    float* V  = sm + 12480;           // reflectors [k][r], pitch 65

    __shared__ float diag[64], off[64], b2[64], eig[64], tauv[64];
    __shared__ float red[32];
    __shared__ int   oflag[64];
    __shared__ float sc_lo, sc_hi;

    int tid = threadIdx.x, lane = tid & 31, warp = tid >> 5;

    if (tid < 64) { diag[tid] = g_diag[tid]; off[tid] = g_off[tid]; }
    if (tid < 62) tauv[tid] = g_tau[tid];
    for (int e = tid; e < 62 * NB; e += 1024)
        V[(e >> 6) * 65 + (e & 63)] = g_V[e];
    __syncthreads();
    if (tid < 63) b2[tid] = off[tid] * off[tid];
    if (tid == 0) {
        float lo = 1e30f, hi = -1e30f;
        for (int i = 0; i < 64; i++) {
            float om = (i > 0) ? fabsf(off[i - 1]) : 0.f;
            float op = (i < 63) ? fabsf(off[i]) : 0.f;
            lo = fminf(lo, diag[i] - om - op);
            hi = fmaxf(hi, diag[i] + om + op);
        }
        float mg = 1e-6f * fmaxf(fabsf(lo), fabsf(hi)) + 1e-30f;
        sc_lo = lo - mg; sc_hi = hi + mg;
    }
    __syncthreads();

    // ---- multisection Sturm: 8 threads per eigenvalue ----
    if (tid < 512) {
        int i = tid >> 3, s8 = tid & 7;
        float lo = sc_lo, hi = sc_hi;
        for (int round = 0; round < NROUNDS; round++) {
            float step = (hi - lo) * (1.f / 9.f);
            float mid = lo + step * (float)(s8 + 1);
            float d = diag[0] - mid;
            int cnt = (d < 0.f);
            for (int j = 1; j < 64; j++) {
                float dg = (fabsf(d) < 1e-25f) ? -1e-25f : d;
                d = (diag[j] - mid) - __fdividef(b2[j - 1], dg);
                cnt += (d < 0.f);
            }
            unsigned bal = __ballot_sync(0xFFFFFFFFu, cnt <= i);
            unsigned bits = (bal >> (lane & 24)) & 0xFFu;
            int p = __popc(bits);
            lo = lo + step * (float)p;
            hi = lo + step;
        }
        if (s8 == 0) eig[i] = 0.5f * (lo + hi);
    }
    __syncthreads();

    // ---- inverse iteration ----
    if (tid < 64) {
        int i = tid;
        float scale = fmaxf(fabsf(sc_hi), fabsf(sc_lo));
        float lam = eig[i] + scale * 2e-6f;
        unsigned h = (unsigned)(i * 2654435761u) ^ 0x9E3779B9u;
        for (int j = 0; j < 64; j++) {
            h = h * 1664525u + 1013904223u;
            E[j * 65 + i] = 1.f + (float)(h >> 16) * 1.52587890625e-05f;
        }
        for (int iter = 0; iter < 3; iter++) {
            float dprev = diag[0] - lam;
            dprev = (fabsf(dprev) < 1e-20f) ? copysignf(1e-20f, dprev) : dprev;
            DD[i * 65 + 0] = dprev;
            float yprev = E[0 * 65 + i];
            YY[i * 65 + 0] = yprev;
            for (int j = 1; j < 64; j++) {
                float m = __fdividef(off[j - 1], dprev);
                float dcur = (diag[j] - lam) - m * off[j - 1];
                dcur = (fabsf(dcur) < 1e-20f) ? copysignf(1e-20f, dcur) : dcur;
                float ycur = E[j * 65 + i] - m * yprev;
                DD[i * 65 + j] = dcur;
                YY[i * 65 + j] = ycur;
                dprev = dcur; yprev = ycur;
            }
            float vj = __fdividef(YY[i * 65 + 63], DD[i * 65 + 63]);
            E[63 * 65 + i] = vj;
            float nrm = vj * vj;
            for (int j = 62; j >= 0; j--) {
                vj = __fdividef(YY[i * 65 + j] - off[j] * vj, DD[i * 65 + j]);
                E[j * 65 + i] = vj;
                nrm += vj * vj;
            }
            float inv = rsqrtf(nrm);
            for (int j = 0; j < 64; j++) E[j * 65 + i] *= inv;
        }
    }
    __syncthreads();

    // ---- gap-flagged neighbor re-orthogonalization ----
    if (tid < 64) {
        float scale = fmaxf(fabsf(eig[63]), fabsf(eig[0]));
        oflag[tid] = (tid > 0) && (eig[tid] - eig[tid - 1] < 1e-3f * scale);
    }
    __syncthreads();
    for (int i = 1; i < 64; i++) {
        if (!oflag[i]) continue;
        float pr = (tid < 64) ? E[tid * 65 + i] * E[tid * 65 + i - 1] : 0.f;
#pragma unroll
        for (int o = 16; o > 0; o >>= 1)
            pr += __shfl_down_sync(0xFFFFFFFFu, pr, o);
        if (lane == 0 && tid < 64) red[warp] = pr;
        __syncthreads();
        float dot = red[0] + red[1];
        float nv = 0.f;
        if (tid < 64) {
            E[tid * 65 + i] -= dot * E[tid * 65 + i - 1];
            nv = E[tid * 65 + i] * E[tid * 65 + i];
        }
#pragma unroll
        for (int o = 16; o > 0; o >>= 1)
            nv += __shfl_down_sync(0xFFFFFFFFu, nv, o);
        if (lane == 0 && tid < 64) red[warp] = nv;
        __syncthreads();
        float sc = rsqrtf(red[0] + red[1] + 1e-30f);
        if (tid < 64) E[tid * 65 + i] *= sc;
        __syncthreads();
    }

    // ---- back-transform: apply reflectors k = 61..0 (cols independent) --
    {
        int col = tid >> 4, sub = tid & 15;
        for (int k = 61; k >= 0; k--) {
            int n0 = k + 1, n2 = 63 - k;
            float tau = tauv[k];
            float acc = 0.f;
            for (int r = sub; r < n2; r += 16)
                acc += V[k * 65 + n0 + r] * E[(n0 + r) * 65 + col];
#pragma unroll
            for (int o = 8; o > 0; o >>= 1)
                acc += __shfl_xor_sync(0xFFFFFFFFu, acc, o, 16);
            float w = tau * acc;
            for (int r = sub; r < n2; r += 16)
                E[(n0 + r) * 65 + col] -= w * V[k * 65 + n0 + r];
        }
    }
    __syncthreads();

    if (tid == 0) {
        g_poles[0] = 0.f;
        float s = 0.f;
        for (int k = 1; k < 64; k++) {
            float p = fmaxf(eig[k], 1e-12f);
            g_poles[k] = p;
            s += p;
        }
        g_trA = s;
    }
    for (int e = tid; e < NB * NB; e += 1024)
        g_Wg[e] = E[(e >> 6) * 65 + (e & 63)];
}

// ------ 5) build U^T  <<<63,256>>>  (full unroll -> deep MLP) ------------
__global__ void k_buildU() {
    __shared__ float wcol[NB];
    int k = blockIdx.x, d = threadIdx.x;
    if (d < NB) wcol[d] = g_Wg[d * NB + (k + 1)];   // ascending columns
    __syncthreads();
    float acc = 0.f;
#pragma unroll
    for (int i = 0; i < NB; i++) acc += __ldg(&g_D0[i * D_ + d]) * wcol[i];
    float lam = g_poles[k + 1];
    g_UT[k * D_ + d] = acc * ALPHA_8 * rsqrtf(fmaxf(lam, 1e-20f));
}

// ------ 6) fused weights + secular, 2 timesteps/block <<<512,256>>> ------
__global__ void k_wsec(float* __restrict__ out) {
    __shared__ float smv0[D_], smv1[D_];
    __shared__ float zsh0[64], zsh1[64];
    __shared__ float red0[8], red1[8];
    __shared__ float w2s[2][NB], ds[NB], vals[2][NB];
    __shared__ float msqs[2];
    int bid = blockIdx.x, tid = threadIdx.x;
    int warp = tid >> 5, lane = tid & 31;
    int t0 = bid * 2;

    float mv0 = g_M[t0 * D_ + tid];
    float mv1 = g_M[(t0 + 1) * D_ + tid];
    smv0[tid] = mv0; smv1[tid] = mv1;
    float p0 = mv0 * mv0, p1 = mv1 * mv1;
#pragma unroll
    for (int o = 16; o > 0; o >>= 1) {
        p0 += __shfl_down_sync(0xFFFFFFFFu, p0, o);
        p1 += __shfl_down_sync(0xFFFFFFFFu, p1, o);
    }
    if (lane == 0) { red0[warp] = p0; red1[warp] = p1; }
    if (tid < NB) ds[tid] = g_poles[tid];
    __syncthreads();

    // z_k = U_k . m  (warp-per-k; UT row loaded once, used for both t)
#pragma unroll
    for (int it = 0; it < 8; it++) {
        int k = warp * 8 + it;
        if (k < 63) {
            float a0 = 0.f, a1 = 0.f;
#pragma unroll
            for (int j = 0; j < 8; j++) {
                float u = g_UT[k * D_ + lane + 32 * j];
                a0 += u * smv0[lane + 32 * j];
                a1 += u * smv1[lane + 32 * j];
            }
#pragma unroll
            for (int o = 16; o > 0; o >>= 1) {
                a0 += __shfl_down_sync(0xFFFFFFFFu, a0, o);
                a1 += __shfl_down_sync(0xFFFFFFFFu, a1, o);
            }
            if (lane == 0) { zsh0[k] = a0; zsh1[k] = a1; }
        }
    }
    __syncthreads();

    // weights: threads 0..63 -> t0, 64..127 -> t1
    if (tid == 0) {
        float msq = 0.f;
#pragma unroll
        for (int w = 0; w < 8; w++) msq += red0[w];
        float sz = 0.f;
        for (int k = 0; k < 63; k++) sz += zsh0[k] * zsh0[k];
        w2s[0][0] = fmaxf(msq - sz, 0.f);
        msqs[0] = msq;
    } else if (tid == 64) {
        float msq = 0.f;
#pragma unroll
        for (int w = 0; w < 8; w++) msq += red1[w];
        float sz = 0.f;
        for (int k = 0; k < 63; k++) sz += zsh1[k] * zsh1[k];
        w2s[1][0] = fmaxf(msq - sz, 0.f);
        msqs[1] = msq;
    } else if (tid < 64) {
        float z = zsh0[tid - 1];
        w2s[0][tid] = z * z;
    } else if (tid < 128) {
        int i = tid - 64;
        float z = zsh1[i - 1];
        w2s[1][i] = z * z;
    }
    __syncthreads();

    if (tid >= 128) return;   // past the last full barrier, safe to retire

    int sel = tid >> 6, i = tid & 63;
    float S = 0.f;
#pragma unroll 8
    for (int k = 0; k < NB; k++) S += w2s[sel][k];

    float lo = ds[i];
    float hi = (i < 63) ? ds[i + 1] : ds[63] + S;
    float lam = 0.5f * (lo + hi);

    for (int it = 0; it < NIT; it++) {
        float f = 1.f, fp = 0.f;
#pragma unroll 8
        for (int k = 0; k < NB; k++) {
            float diff = ds[k] - lam;
            float rc;
            asm("rcp.approx.f32 %0, %1;" : "=f"(rc) : "f"(diff));
            float term = w2s[sel][k] * rc;
            f  += term;
            fp += term * rc;
        }
        if (f > 0.f) hi = lam; else lo = lam;
        float ln = lam - __fdividef(f, fp);
        lam = (ln > lo && ln < hi) ? ln : 0.5f * (lo + hi);
    }

    float tr = msqs[sel] + g_trA;
    float v = fmaxf(__fdividef(lam, tr), EPSV);
    vals[sel][i] = v;
    __threadfence_block();
    asm volatile("bar.sync 1, 128;" ::: "memory");

    float ssum = 192.f * EPSV;
#pragma unroll 8
    for (int k = 0; k < NB; k++) ssum += vals[sel][k];
    float inv = __frcp_rn(ssum);

    float* o = out + (long)(t0 + sel) * D_;
    float ev = EPSV * inv;
    o[i]        = ev;               // positions   0..63  (zero eigs)
    o[i + 64]   = ev;               // positions  64..127
    o[i + 128]  = ev;               // positions 128..191
    o[i + 192]  = vals[sel][i] * inv;  // positions 192..255 (roots, ascending)
}

// ---------------- launcher ----------------
extern "C" void kernel_launch(void* const* d_in, const int* in_sizes, int n_in,
                              void* d_out, int out_size) {
    const int*   tokens = (const int*)d_in[0];
    const float* embed  = (const float*)d_in[1];
    const float* bubbles= (const float*)d_in[2];
    const float* mdecay = (const float*)d_in[3];
    float* out = (float*)d_out;

    cudaFuncSetAttribute(k_eigvec, cudaFuncAttributeMaxDynamicSharedMemorySize,
                         66560);

    k_scan     <<<32, 256>>>(tokens, embed, bubbles, mdecay);
    k_gramsetup<<<64, 64>>>(bubbles);
    k_tridiag  <<<1, 64>>>();
    k_eigvec   <<<1, 1024, 66560>>>();
    k_buildU   <<<63, 256>>>();
    k_wsec     <<<512, 256>>>(out);
    (void)in_sizes; (void)n_in; (void)out_size;
}